// round 2
// baseline (speedup 1.0000x reference)
#include <cuda_runtime.h>
#include <cuda_bf16.h>
#include <math.h>

#define BATCH 2
#define SEQ   2048
#define DIM   1024
#define NHEAD 16
#define HD    64
#define MROWS (BATCH * SEQ)   // 4096

// ---------------- scratch (device globals; no runtime allocation) ----------
__device__ float g_q[MROWS * DIM];
__device__ float g_k[MROWS * DIM];
__device__ float g_v[MROWS * DIM];
__device__ float g_ctx[MROWS * DIM];

// ---------------- SGEMM + bias: C[M,N] = A[M,K] @ B[K,N] + bias[N] ---------
// 128x128x16 tiles, 8x8 microtile, 256 threads, smem double-buffered.
#define BM 128
#define BN 128
#define BK 16
#define TM 8
#define TN 8

__global__ __launch_bounds__(256) void sgemm_bias_kernel(
    const float* __restrict__ A, const float* __restrict__ B,
    const float* __restrict__ bias, float* __restrict__ C,
    int M, int N, int K)
{
    __shared__ float As[2][BK][BM];   // transposed A tile
    __shared__ float Bs[2][BK][BN];

    const int tid = threadIdx.x;
    const int tr  = tid >> 4;      // 0..15
    const int tc  = tid & 15;      // 0..15
    const int blockRow = blockIdx.y * BM;
    const int blockCol = blockIdx.x * BN;

    const int a_r = tid >> 2;          // 0..63
    const int a_c = (tid & 3) << 2;    // 0,4,8,12
    const int b_r = tid >> 5;          // 0..7
    const int b_c = (tid & 31) << 2;   // 0..124

    float acc[TM][TN];
    #pragma unroll
    for (int i = 0; i < TM; i++)
        #pragma unroll
        for (int j = 0; j < TN; j++) acc[i][j] = 0.f;

    const int nTiles = K / BK;

    // preload tile 0 into buffer 0
    #pragma unroll
    for (int s = 0; s < 2; s++) {
        int r = a_r + s * 64;
        float4 v = *(const float4*)(A + (size_t)(blockRow + r) * K + a_c);
        As[0][a_c + 0][r] = v.x;
        As[0][a_c + 1][r] = v.y;
        As[0][a_c + 2][r] = v.z;
        As[0][a_c + 3][r] = v.w;
    }
    #pragma unroll
    for (int s = 0; s < 2; s++) {
        int r = b_r + s * 8;
        *(float4*)(&Bs[0][r][b_c]) =
            *(const float4*)(B + (size_t)r * N + blockCol + b_c);
    }
    __syncthreads();

    for (int t = 0; t < nTiles; t++) {
        const int cur = t & 1;
        float4 a_pref[2], b_pref[2];
        const bool more = (t + 1 < nTiles);
        if (more) {
            const int k0 = (t + 1) * BK;
            #pragma unroll
            for (int s = 0; s < 2; s++)
                a_pref[s] = *(const float4*)(A + (size_t)(blockRow + a_r + s * 64) * K + k0 + a_c);
            #pragma unroll
            for (int s = 0; s < 2; s++)
                b_pref[s] = *(const float4*)(B + (size_t)(k0 + b_r + s * 8) * N + blockCol + b_c);
        }

        #pragma unroll
        for (int k = 0; k < BK; k++) {
            float rm[TM], rn[TN];
            #pragma unroll
            for (int i = 0; i < TM; i += 4)
                *(float4*)(&rm[i]) = *(const float4*)(&As[cur][k][tr * TM + i]);
            #pragma unroll
            for (int j = 0; j < TN; j += 4)
                *(float4*)(&rn[j]) = *(const float4*)(&Bs[cur][k][tc * TN + j]);
            #pragma unroll
            for (int i = 0; i < TM; i++)
                #pragma unroll
                for (int j = 0; j < TN; j++)
                    acc[i][j] += rm[i] * rn[j];
        }

        if (more) {
            const int nxt = cur ^ 1;
            #pragma unroll
            for (int s = 0; s < 2; s++) {
                int r = a_r + s * 64;
                As[nxt][a_c + 0][r] = a_pref[s].x;
                As[nxt][a_c + 1][r] = a_pref[s].y;
                As[nxt][a_c + 2][r] = a_pref[s].z;
                As[nxt][a_c + 3][r] = a_pref[s].w;
            }
            #pragma unroll
            for (int s = 0; s < 2; s++)
                *(float4*)(&Bs[nxt][b_r + s * 8][b_c]) = b_pref[s];
        }
        __syncthreads();
    }

    #pragma unroll
    for (int i = 0; i < TM; i++) {
        int row = blockRow + tr * TM + i;
        #pragma unroll
        for (int j = 0; j < TN; j += 4) {
            int col = blockCol + tc * TN + j;
            float4 bv = *(const float4*)(bias + col);
            float4 o;
            o.x = acc[i][j + 0] + bv.x;
            o.y = acc[i][j + 1] + bv.y;
            o.z = acc[i][j + 2] + bv.z;
            o.w = acc[i][j + 3] + bv.w;
            *(float4*)(C + (size_t)row * N + col) = o;
        }
    }
}

// ---------------- Flash attention (fp32, causal, softmax-one) --------------
// grid: (SEQ/64, BATCH*NHEAD), block 128 threads.
// Transposed (d-major) smem layout: all inner-loop reads are float4, with Q/P
// reads warp-broadcast and K/V reads conflict-free.
#define FS 68   // padded row stride (floats): 16B-aligned, bank-skewed
#define ATT_SMEM_FLOATS (4 * 64 * FS)

__global__ __launch_bounds__(128) void flash_attn_kernel(
    const float* __restrict__ Q, const float* __restrict__ K,
    const float* __restrict__ V, float* __restrict__ O)
{
    const int qt  = blockIdx.x;            // q tile 0..31
    const int bh  = blockIdx.y;            // 0..31
    const int b   = bh >> 4;
    const int h   = bh & 15;
    const int tid = threadIdx.x;
    const int tx  = tid & 15;
    const int ty  = tid >> 4;              // 0..7

    extern __shared__ float sm[];
    float* QsT = sm;                        // [64 d][FS] : QsT[d*FS + row]
    float* KsT = QsT + 64 * FS;             // [64 d][FS] : KsT[d*FS + n]
    float* Vs  = KsT + 64 * FS;             // [64 k][FS] : Vs[k*FS + d]
    float* PsT = Vs  + 64 * FS;             // [64 k][FS] : PsT[k*FS + row]

    const int qbase = qt * 64;
    const size_t head_off = ((size_t)b * SEQ) * DIM + (size_t)h * HD;

    // load + prescale Q tile, transposed (1/sqrt(64) = 0.125)
    #pragma unroll
    for (int s = 0; s < 8; s++) {
        int f  = tid + s * 128;            // 1024 float4 slots
        int r  = f >> 4;
        int c4 = (f & 15) << 2;
        float4 v = *(const float4*)(Q + head_off + (size_t)(qbase + r) * DIM + c4);
        QsT[(c4 + 0) * FS + r] = v.x * 0.125f;
        QsT[(c4 + 1) * FS + r] = v.y * 0.125f;
        QsT[(c4 + 2) * FS + r] = v.z * 0.125f;
        QsT[(c4 + 3) * FS + r] = v.w * 0.125f;
    }

    float o[8][4];
    float m[8], l[8];
    #pragma unroll
    for (int i = 0; i < 8; i++) {
        m[i] = -INFINITY; l[i] = 0.f;
        #pragma unroll
        for (int j = 0; j < 4; j++) o[i][j] = 0.f;
    }

    for (int kt = 0; kt <= qt; kt++) {
        const int kbase = kt * 64;
        __syncthreads();   // prior iter consumers done (covers Qs on iter 0)

        #pragma unroll
        for (int s = 0; s < 8; s++) {
            int f  = tid + s * 128;
            int r  = f >> 4;
            int c4 = (f & 15) << 2;
            float4 kv = *(const float4*)(K + head_off + (size_t)(kbase + r) * DIM + c4);
            KsT[(c4 + 0) * FS + r] = kv.x;
            KsT[(c4 + 1) * FS + r] = kv.y;
            KsT[(c4 + 2) * FS + r] = kv.z;
            KsT[(c4 + 3) * FS + r] = kv.w;
            float4 vv = *(const float4*)(V + head_off + (size_t)(kbase + r) * DIM + c4);
            *(float4*)(Vs + r * FS + c4) = vv;
        }
        __syncthreads();

        // S = Q @ K^T   (8 rows x 4 cols per thread)
        float s_[8][4];
        #pragma unroll
        for (int i = 0; i < 8; i++)
            #pragma unroll
            for (int j = 0; j < 4; j++) s_[i][j] = 0.f;

        #pragma unroll 4
        for (int d = 0; d < 64; d++) {
            float4 kv = *(const float4*)(KsT + d * FS + 4 * tx);
            float qreg[8];
            *(float4*)(qreg)     = *(const float4*)(QsT + d * FS + ty * 8);
            *(float4*)(qreg + 4) = *(const float4*)(QsT + d * FS + ty * 8 + 4);
            #pragma unroll
            for (int i = 0; i < 8; i++) {
                s_[i][0] += qreg[i] * kv.x;
                s_[i][1] += qreg[i] * kv.y;
                s_[i][2] += qreg[i] * kv.z;
                s_[i][3] += qreg[i] * kv.w;
            }
        }

        // causal mask — only the diagonal tile is partially masked
        if (kt == qt) {
            #pragma unroll
            for (int i = 0; i < 8; i++)
                #pragma unroll
                for (int j = 0; j < 4; j++)
                    if (4 * tx + j > ty * 8 + i) s_[i][j] = -INFINITY;
        }

        // online softmax-one update; write P transposed
        #pragma unroll
        for (int i = 0; i < 8; i++) {
            float rm = fmaxf(fmaxf(s_[i][0], s_[i][1]), fmaxf(s_[i][2], s_[i][3]));
            #pragma unroll
            for (int off = 8; off > 0; off >>= 1)
                rm = fmaxf(rm, __shfl_xor_sync(0xffffffffu, rm, off));
            float mnew = fmaxf(m[i], rm);
            float ps = 0.f;
            #pragma unroll
            for (int j = 0; j < 4; j++) {
                float p = __expf(s_[i][j] - mnew);
                PsT[(4 * tx + j) * FS + ty * 8 + i] = p;
                ps += p;
            }
            #pragma unroll
            for (int off = 8; off > 0; off >>= 1)
                ps += __shfl_xor_sync(0xffffffffu, ps, off);
            float corr = __expf(m[i] - mnew);   // 0 when m was -inf
            l[i] = l[i] * corr + ps;
            m[i] = mnew;
            #pragma unroll
            for (int j = 0; j < 4; j++) o[i][j] *= corr;
        }
        __syncthreads();   // P visible to all

        // O += P @ V
        #pragma unroll 4
        for (int kk = 0; kk < 64; kk++) {
            float4 rv = *(const float4*)(Vs + kk * FS + 4 * tx);
            float preg[8];
            *(float4*)(preg)     = *(const float4*)(PsT + kk * FS + ty * 8);
            *(float4*)(preg + 4) = *(const float4*)(PsT + kk * FS + ty * 8 + 4);
            #pragma unroll
            for (int i = 0; i < 8; i++) {
                o[i][0] += preg[i] * rv.x;
                o[i][1] += preg[i] * rv.y;
                o[i][2] += preg[i] * rv.z;
                o[i][3] += preg[i] * rv.w;
            }
        }
    }

    // epilogue: divide by (1 + l) — softmax-one denominator
    #pragma unroll
    for (int i = 0; i < 8; i++) {
        float inv = 1.f / (1.f + l[i]);
        float4 w;
        w.x = o[i][0] * inv;
        w.y = o[i][1] * inv;
        w.z = o[i][2] * inv;
        w.w = o[i][3] * inv;
        *(float4*)(O + head_off + (size_t)(qbase + ty * 8 + i) * DIM + 4 * tx) = w;
    }
}

// ---------------- launcher -------------------------------------------------
extern "C" void kernel_launch(void* const* d_in, const int* in_sizes, int n_in,
                              void* d_out, int out_size)
{
    const float* x  = (const float*)d_in[0];
    const float* Wq = (const float*)d_in[1];
    const float* bq = (const float*)d_in[2];
    const float* Wk = (const float*)d_in[3];
    const float* bk = (const float*)d_in[4];
    const float* Wv = (const float*)d_in[5];
    const float* bv = (const float*)d_in[6];
    const float* Wo = (const float*)d_in[7];
    const float* bo = (const float*)d_in[8];
    float* out = (float*)d_out;

    float *q, *k, *v, *ctx;
    cudaGetSymbolAddress((void**)&q,   g_q);
    cudaGetSymbolAddress((void**)&k,   g_k);
    cudaGetSymbolAddress((void**)&v,   g_v);
    cudaGetSymbolAddress((void**)&ctx, g_ctx);

    const int smem = ATT_SMEM_FLOATS * (int)sizeof(float);
    cudaFuncSetAttribute(flash_attn_kernel,
                         cudaFuncAttributeMaxDynamicSharedMemorySize, smem);

    dim3 gemmGrid(DIM / BN, MROWS / BM);    // (8, 32)
    sgemm_bias_kernel<<<gemmGrid, 256>>>(x, Wq, bq, q, MROWS, DIM, DIM);
    sgemm_bias_kernel<<<gemmGrid, 256>>>(x, Wk, bk, k, MROWS, DIM, DIM);
    sgemm_bias_kernel<<<gemmGrid, 256>>>(x, Wv, bv, v, MROWS, DIM, DIM);

    dim3 attnGrid(SEQ / 64, BATCH * NHEAD); // (32, 32)
    flash_attn_kernel<<<attnGrid, 128, smem>>>(q, k, v, ctx);

    sgemm_bias_kernel<<<gemmGrid, 256>>>(ctx, Wo, bo, out, MROWS, DIM, DIM);
}

// round 4
// speedup vs baseline: 1.5426x; 1.5426x over previous
#include <cuda_runtime.h>
#include <cuda_bf16.h>
#include <math.h>
#include <stdint.h>

#define BATCH 2
#define SEQ   2048
#define DIM   1024
#define NHEAD 16
#define HD    64
#define MROWS (BATCH * SEQ)   // 4096

// ---------------- scratch (device globals; no runtime allocation) ----------
__device__ float g_q[MROWS * DIM];
__device__ float g_k[MROWS * DIM];
__device__ float g_v[MROWS * DIM];
__device__ float g_ctx[MROWS * DIM];
__device__ __nv_bfloat16 g_xh[MROWS * DIM];
__device__ __nv_bfloat16 g_xl[MROWS * DIM];
__device__ __nv_bfloat16 g_wth[4 * DIM * DIM];
__device__ __nv_bfloat16 g_wtl[4 * DIM * DIM];

// ---------------- PTX helpers (sm_80-era only; no 'a'-gated features) ------
__device__ __forceinline__ uint32_t smem_u32(const void* p) {
    uint32_t a;
    asm("{ .reg .u64 t; cvta.to.shared.u64 t, %1; cvt.u32.u64 %0, t; }"
        : "=r"(a) : "l"(p));
    return a;
}
__device__ __forceinline__ void cp_async16(uint32_t saddr, const void* gptr) {
    asm volatile("cp.async.cg.shared.global [%0], [%1], 16;"
                 :: "r"(saddr), "l"(gptr));
}
__device__ __forceinline__ void cp_commit() {
    asm volatile("cp.async.commit_group;");
}
template <int N>
__device__ __forceinline__ void cp_wait() {
    asm volatile("cp.async.wait_group %0;" :: "n"(N));
}
__device__ __forceinline__ void ldsm4(uint32_t* r, uint32_t addr) {
    asm volatile("ldmatrix.sync.aligned.m8n8.x4.shared.b16 {%0,%1,%2,%3}, [%4];"
                 : "=r"(r[0]), "=r"(r[1]), "=r"(r[2]), "=r"(r[3]) : "r"(addr));
}
__device__ __forceinline__ void mma16816(float* c, const uint32_t* a, const uint32_t* b) {
    asm volatile(
        "mma.sync.aligned.m16n8k16.row.col.f32.bf16.bf16.f32 "
        "{%0,%1,%2,%3}, {%4,%5,%6,%7}, {%8,%9}, {%0,%1,%2,%3};"
        : "+f"(c[0]), "+f"(c[1]), "+f"(c[2]), "+f"(c[3])
        : "r"(a[0]), "r"(a[1]), "r"(a[2]), "r"(a[3]), "r"(b[0]), "r"(b[1]));
}

// ---------------- split / transpose-split kernels ---------------------------
__global__ __launch_bounds__(256) void split_kernel(
    const float4* __restrict__ in, __nv_bfloat16* __restrict__ hi,
    __nv_bfloat16* __restrict__ lo, int n4)
{
    int i = blockIdx.x * blockDim.x + threadIdx.x;
    if (i >= n4) return;
    float4 v = in[i];
    float f[4] = {v.x, v.y, v.z, v.w};
    __nv_bfloat162 h2[2], l2[2];
    #pragma unroll
    for (int j = 0; j < 4; j++) {
        __nv_bfloat16 h = __float2bfloat16_rn(f[j]);
        __nv_bfloat16 l = __float2bfloat16_rn(f[j] - __bfloat162float(h));
        ((__nv_bfloat16*)h2)[j] = h;
        ((__nv_bfloat16*)l2)[j] = l;
    }
    ((__nv_bfloat162*)hi)[2 * i + 0] = h2[0];
    ((__nv_bfloat162*)hi)[2 * i + 1] = h2[1];
    ((__nv_bfloat162*)lo)[2 * i + 0] = l2[0];
    ((__nv_bfloat162*)lo)[2 * i + 1] = l2[1];
}

// W[K,N] fp32 -> Th/Tl [N,K] bf16
__global__ __launch_bounds__(256) void transpose_split_kernel(
    const float* __restrict__ W, __nv_bfloat16* __restrict__ Th,
    __nv_bfloat16* __restrict__ Tl)
{
    __shared__ float t[32][33];
    const int tx = threadIdx.x, ty = threadIdx.y;
    const int bx = blockIdx.x * 32, by = blockIdx.y * 32;
    #pragma unroll
    for (int s = 0; s < 4; s++)
        t[ty + s * 8][tx] = W[(size_t)(by + ty + s * 8) * DIM + bx + tx];
    __syncthreads();
    #pragma unroll
    for (int s = 0; s < 4; s++) {
        float v = t[tx][ty + s * 8];
        __nv_bfloat16 h = __float2bfloat16_rn(v);
        __nv_bfloat16 l = __float2bfloat16_rn(v - __bfloat162float(h));
        size_t o = (size_t)(bx + ty + s * 8) * DIM + by + tx;
        Th[o] = h; Tl[o] = l;
    }
}

// ---------------- mma.sync bf16-split GEMM: C = A@W + bias -----------------
// A = (Ah+Al)[M,K] bf16, W = (Bh+Bl)[N,K] bf16 (pre-transposed), C fp32.
// Block 128x128, 8 warps (2x4), warp tile 64x32, K-chunk 64.
// 48 virtual chunks: phase 0: Ah*Bh, 1: Ah*Bl, 2: Al*Bh (fp32 accumulate).
#define GS       72                       // smem row stride (bf16 elems) = 144B
#define GTILE_B  (128 * GS * 2)           // bytes per tile (18432)
#define GBUF_B   (2 * GTILE_B)            // A+B per buffer (36864)
#define GEMM_SMEM (2 * GBUF_B)            // 73728

__global__ __launch_bounds__(256, 1)
void gemm_mma_kernel(const __nv_bfloat16* __restrict__ Ah,
                     const __nv_bfloat16* __restrict__ Al,
                     const __nv_bfloat16* __restrict__ Bh,
                     const __nv_bfloat16* __restrict__ Bl,
                     const float* __restrict__ bias, float* __restrict__ C)
{
    extern __shared__ char smem[];
    const uint32_t sbase = smem_u32(smem);

    const int tid  = threadIdx.x;
    const int wid  = tid >> 5;
    const int lane = tid & 31;
    const int blockRow = blockIdx.y * 128;
    const int blockCol = blockIdx.x * 128;
    const int wrow = (wid >> 2) * 64;     // 0 / 64
    const int wcol = (wid & 3) * 32;      // 0 / 32 / 64 / 96

    float acc[4][4][4];
    #pragma unroll
    for (int mi = 0; mi < 4; mi++)
        #pragma unroll
        for (int ni = 0; ni < 4; ni++)
            #pragma unroll
            for (int j = 0; j < 4; j++) acc[mi][ni][j] = 0.f;

    // per-thread load mapping: 4 segs/tile, seg idx = tid + i*256
    // row = idx>>3 (0..127), seg = idx&7 ; smem off = row*144 + seg*16
    // chunk source select
    #define CHUNK_SRC(c, Asrc, Bsrc, koff) { \
        int ph = (c) >> 4; koff = ((c) & 15) * 64; \
        Asrc = (ph == 2) ? Al : Ah; \
        Bsrc = (ph == 1) ? Bl : Bh; }

    #define ISSUE_CHUNK(c, buf) { \
        const __nv_bfloat16 *As_, *Bs_; int ko_; \
        CHUNK_SRC(c, As_, Bs_, ko_); \
        uint32_t s0 = sbase + (buf) * GBUF_B; \
        _Pragma("unroll") \
        for (int i = 0; i < 4; i++) { \
            int idx = tid + i * 256; \
            int row = idx >> 3, seg = idx & 7; \
            cp_async16(s0 + row * 144 + seg * 16, \
                       As_ + (size_t)(blockRow + row) * DIM + ko_ + seg * 8); \
            cp_async16(s0 + GTILE_B + row * 144 + seg * 16, \
                       Bs_ + (size_t)(blockCol + row) * DIM + ko_ + seg * 8); \
        } }

    // ldmatrix per-thread addresses
    const int aRow = wrow + (lane & 15);
    const int aCol = (lane >> 4) * 8;
    const int bRow = wcol + (lane >> 4) * 8 + (lane & 7);
    const int bCol = ((lane >> 3) & 1) * 8;

    ISSUE_CHUNK(0, 0);
    cp_commit();

    for (int c = 0; c < 48; c++) {
        if (c + 1 < 48) { ISSUE_CHUNK(c + 1, (c + 1) & 1); }
        cp_commit();
        if (c + 1 < 48) cp_wait<1>(); else cp_wait<0>();
        __syncthreads();

        const uint32_t s0 = sbase + (c & 1) * GBUF_B;
        #pragma unroll
        for (int kk = 0; kk < 4; kk++) {
            uint32_t a[4][4], b[2][4];
            #pragma unroll
            for (int mi = 0; mi < 4; mi++)
                ldsm4(a[mi], s0 + ((aRow + mi * 16) * GS + kk * 16 + aCol) * 2);
            #pragma unroll
            for (int np = 0; np < 2; np++)
                ldsm4(b[np], s0 + GTILE_B +
                      ((bRow + np * 16) * GS + kk * 16 + bCol) * 2);
            #pragma unroll
            for (int mi = 0; mi < 4; mi++)
                #pragma unroll
                for (int ni = 0; ni < 4; ni++)
                    mma16816(acc[mi][ni], a[mi], &b[ni >> 1][(ni & 1) * 2]);
        }
        __syncthreads();
    }

    // epilogue: add bias, store fp32
    #pragma unroll
    for (int mi = 0; mi < 4; mi++) {
        const int r0 = blockRow + wrow + mi * 16 + (lane >> 2);
        #pragma unroll
        for (int ni = 0; ni < 4; ni++) {
            const int c0 = blockCol + wcol + ni * 8 + 2 * (lane & 3);
            float2 bv = *(const float2*)(bias + c0);
            float2 v0 = { acc[mi][ni][0] + bv.x, acc[mi][ni][1] + bv.y };
            float2 v1 = { acc[mi][ni][2] + bv.x, acc[mi][ni][3] + bv.y };
            *(float2*)(C + (size_t)r0 * DIM + c0)       = v0;
            *(float2*)(C + (size_t)(r0 + 8) * DIM + c0) = v1;
        }
    }
}

// ---------------- Flash attention (fp32, causal, softmax-one) --------------
#define FS 68
#define ATT_SMEM_FLOATS (4 * 64 * FS)

__global__ __launch_bounds__(128) void flash_attn_kernel(
    const float* __restrict__ Q, const float* __restrict__ K,
    const float* __restrict__ V, float* __restrict__ O)
{
    const int qt  = blockIdx.x;
    const int bh  = blockIdx.y;
    const int b   = bh >> 4;
    const int h   = bh & 15;
    const int tid = threadIdx.x;
    const int tx  = tid & 15;
    const int ty  = tid >> 4;

    extern __shared__ float sm[];
    float* QsT = sm;
    float* KsT = QsT + 64 * FS;
    float* Vs  = KsT + 64 * FS;
    float* PsT = Vs  + 64 * FS;

    const int qbase = qt * 64;
    const size_t head_off = ((size_t)b * SEQ) * DIM + (size_t)h * HD;

    #pragma unroll
    for (int s = 0; s < 8; s++) {
        int f  = tid + s * 128;
        int r  = f >> 4;
        int c4 = (f & 15) << 2;
        float4 v = *(const float4*)(Q + head_off + (size_t)(qbase + r) * DIM + c4);
        QsT[(c4 + 0) * FS + r] = v.x * 0.125f;
        QsT[(c4 + 1) * FS + r] = v.y * 0.125f;
        QsT[(c4 + 2) * FS + r] = v.z * 0.125f;
        QsT[(c4 + 3) * FS + r] = v.w * 0.125f;
    }

    float o[8][4];
    float m[8], l[8];
    #pragma unroll
    for (int i = 0; i < 8; i++) {
        m[i] = -INFINITY; l[i] = 0.f;
        #pragma unroll
        for (int j = 0; j < 4; j++) o[i][j] = 0.f;
    }

    for (int kt = 0; kt <= qt; kt++) {
        const int kbase = kt * 64;
        __syncthreads();

        #pragma unroll
        for (int s = 0; s < 8; s++) {
            int f  = tid + s * 128;
            int r  = f >> 4;
            int c4 = (f & 15) << 2;
            float4 kv = *(const float4*)(K + head_off + (size_t)(kbase + r) * DIM + c4);
            KsT[(c4 + 0) * FS + r] = kv.x;
            KsT[(c4 + 1) * FS + r] = kv.y;
            KsT[(c4 + 2) * FS + r] = kv.z;
            KsT[(c4 + 3) * FS + r] = kv.w;
            float4 vv = *(const float4*)(V + head_off + (size_t)(kbase + r) * DIM + c4);
            *(float4*)(Vs + r * FS + c4) = vv;
        }
        __syncthreads();

        float s_[8][4];
        #pragma unroll
        for (int i = 0; i < 8; i++)
            #pragma unroll
            for (int j = 0; j < 4; j++) s_[i][j] = 0.f;

        #pragma unroll 4
        for (int d = 0; d < 64; d++) {
            float4 kv = *(const float4*)(KsT + d * FS + 4 * tx);
            float qreg[8];
            *(float4*)(qreg)     = *(const float4*)(QsT + d * FS + ty * 8);
            *(float4*)(qreg + 4) = *(const float4*)(QsT + d * FS + ty * 8 + 4);
            #pragma unroll
            for (int i = 0; i < 8; i++) {
                s_[i][0] += qreg[i] * kv.x;
                s_[i][1] += qreg[i] * kv.y;
                s_[i][2] += qreg[i] * kv.z;
                s_[i][3] += qreg[i] * kv.w;
            }
        }

        if (kt == qt) {
            #pragma unroll
            for (int i = 0; i < 8; i++)
                #pragma unroll
                for (int j = 0; j < 4; j++)
                    if (4 * tx + j > ty * 8 + i) s_[i][j] = -INFINITY;
        }

        #pragma unroll
        for (int i = 0; i < 8; i++) {
            float rm = fmaxf(fmaxf(s_[i][0], s_[i][1]), fmaxf(s_[i][2], s_[i][3]));
            #pragma unroll
            for (int off = 8; off > 0; off >>= 1)
                rm = fmaxf(rm, __shfl_xor_sync(0xffffffffu, rm, off));
            float mnew = fmaxf(m[i], rm);
            float ps = 0.f;
            #pragma unroll
            for (int j = 0; j < 4; j++) {
                float p = __expf(s_[i][j] - mnew);
                PsT[(4 * tx + j) * FS + ty * 8 + i] = p;
                ps += p;
            }
            #pragma unroll
            for (int off = 8; off > 0; off >>= 1)
                ps += __shfl_xor_sync(0xffffffffu, ps, off);
            float corr = __expf(m[i] - mnew);
            l[i] = l[i] * corr + ps;
            m[i] = mnew;
            #pragma unroll
            for (int j = 0; j < 4; j++) o[i][j] *= corr;
        }
        __syncthreads();

        #pragma unroll 4
        for (int kk = 0; kk < 64; kk++) {
            float4 rv = *(const float4*)(Vs + kk * FS + 4 * tx);
            float preg[8];
            *(float4*)(preg)     = *(const float4*)(PsT + kk * FS + ty * 8);
            *(float4*)(preg + 4) = *(const float4*)(PsT + kk * FS + ty * 8 + 4);
            #pragma unroll
            for (int i = 0; i < 8; i++) {
                o[i][0] += preg[i] * rv.x;
                o[i][1] += preg[i] * rv.y;
                o[i][2] += preg[i] * rv.z;
                o[i][3] += preg[i] * rv.w;
            }
        }
    }

    #pragma unroll
    for (int i = 0; i < 8; i++) {
        float inv = 1.f / (1.f + l[i]);
        float4 w;
        w.x = o[i][0] * inv;
        w.y = o[i][1] * inv;
        w.z = o[i][2] * inv;
        w.w = o[i][3] * inv;
        *(float4*)(O + head_off + (size_t)(qbase + ty * 8 + i) * DIM + 4 * tx) = w;
    }
}

// ---------------- launcher -------------------------------------------------
extern "C" void kernel_launch(void* const* d_in, const int* in_sizes, int n_in,
                              void* d_out, int out_size)
{
    const float* x  = (const float*)d_in[0];
    const float* Wq = (const float*)d_in[1];
    const float* bq = (const float*)d_in[2];
    const float* Wk = (const float*)d_in[3];
    const float* bk = (const float*)d_in[4];
    const float* Wv = (const float*)d_in[5];
    const float* bv = (const float*)d_in[6];
    const float* Wo = (const float*)d_in[7];
    const float* bo = (const float*)d_in[8];
    float* out = (float*)d_out;

    float *q, *k, *v, *ctx;
    __nv_bfloat16 *xh, *xl, *wth, *wtl;
    cudaGetSymbolAddress((void**)&q,   g_q);
    cudaGetSymbolAddress((void**)&k,   g_k);
    cudaGetSymbolAddress((void**)&v,   g_v);
    cudaGetSymbolAddress((void**)&ctx, g_ctx);
    cudaGetSymbolAddress((void**)&xh,  g_xh);
    cudaGetSymbolAddress((void**)&xl,  g_xl);
    cudaGetSymbolAddress((void**)&wth, g_wth);
    cudaGetSymbolAddress((void**)&wtl, g_wtl);

    const int att_smem = ATT_SMEM_FLOATS * (int)sizeof(float);
    cudaFuncSetAttribute(flash_attn_kernel,
                         cudaFuncAttributeMaxDynamicSharedMemorySize, att_smem);
    cudaFuncSetAttribute(gemm_mma_kernel,
                         cudaFuncAttributeMaxDynamicSharedMemorySize, GEMM_SMEM);

    const int n4 = MROWS * DIM / 4;
    dim3 tb(32, 8), tg(32, 32);

    // prep: split x; transpose-split the 4 weights
    split_kernel<<<(n4 + 255) / 256, 256>>>((const float4*)x, xh, xl, n4);
    transpose_split_kernel<<<tg, tb>>>(Wq, wth + 0 * DIM * DIM, wtl + 0 * DIM * DIM);
    transpose_split_kernel<<<tg, tb>>>(Wk, wth + 1 * DIM * DIM, wtl + 1 * DIM * DIM);
    transpose_split_kernel<<<tg, tb>>>(Wv, wth + 2 * DIM * DIM, wtl + 2 * DIM * DIM);
    transpose_split_kernel<<<tg, tb>>>(Wo, wth + 3 * DIM * DIM, wtl + 3 * DIM * DIM);

    dim3 gg(DIM / 128, MROWS / 128);   // (8, 32)
    gemm_mma_kernel<<<gg, 256, GEMM_SMEM>>>(xh, xl, wth + 0 * DIM * DIM, wtl + 0 * DIM * DIM, bq, q);
    gemm_mma_kernel<<<gg, 256, GEMM_SMEM>>>(xh, xl, wth + 1 * DIM * DIM, wtl + 1 * DIM * DIM, bk, k);
    gemm_mma_kernel<<<gg, 256, GEMM_SMEM>>>(xh, xl, wth + 2 * DIM * DIM, wtl + 2 * DIM * DIM, bv, v);

    dim3 attnGrid(SEQ / 64, BATCH * NHEAD);
    flash_attn_kernel<<<attnGrid, 128, att_smem>>>(q, k, v, ctx);

    split_kernel<<<(n4 + 255) / 256, 256>>>((const float4*)ctx, xh, xl, n4);
    gemm_mma_kernel<<<gg, 256, GEMM_SMEM>>>(xh, xl, wth + 3 * DIM * DIM, wtl + 3 * DIM * DIM, bo, out);
}

// round 5
// speedup vs baseline: 2.3873x; 1.5476x over previous
#include <cuda_runtime.h>
#include <cuda_bf16.h>
#include <math.h>
#include <stdint.h>

#define BATCH 2
#define SEQ   2048
#define DIM   1024
#define NHEAD 16
#define HD    64
#define MROWS (BATCH * SEQ)   // 4096

// ---------------- scratch (device globals; no runtime allocation) ----------
__device__ float g_q[MROWS * DIM];
__device__ float g_k[MROWS * DIM];
__device__ float g_v[MROWS * DIM];
__device__ float g_ctx[MROWS * DIM];
__device__ __nv_bfloat16 g_xh[MROWS * DIM];
__device__ __nv_bfloat16 g_xl[MROWS * DIM];
__device__ __nv_bfloat16 g_wth[4 * DIM * DIM];
__device__ __nv_bfloat16 g_wtl[4 * DIM * DIM];

// ---------------- PTX helpers (sm_80-era only; no 'a'-gated features) ------
__device__ __forceinline__ uint32_t smem_u32(const void* p) {
    uint32_t a;
    asm("{ .reg .u64 t; cvta.to.shared.u64 t, %1; cvt.u32.u64 %0, t; }"
        : "=r"(a) : "l"(p));
    return a;
}
__device__ __forceinline__ void cp_async16(uint32_t saddr, const void* gptr) {
    asm volatile("cp.async.cg.shared.global [%0], [%1], 16;"
                 :: "r"(saddr), "l"(gptr));
}
__device__ __forceinline__ void cp_commit() {
    asm volatile("cp.async.commit_group;");
}
template <int N>
__device__ __forceinline__ void cp_wait() {
    asm volatile("cp.async.wait_group %0;" :: "n"(N));
}
__device__ __forceinline__ void ldsm4(uint32_t* r, uint32_t addr) {
    asm volatile("ldmatrix.sync.aligned.m8n8.x4.shared.b16 {%0,%1,%2,%3}, [%4];"
                 : "=r"(r[0]), "=r"(r[1]), "=r"(r[2]), "=r"(r[3]) : "r"(addr));
}
__device__ __forceinline__ void mma16816(float* c, const uint32_t* a, const uint32_t* b) {
    asm volatile(
        "mma.sync.aligned.m16n8k16.row.col.f32.bf16.bf16.f32 "
        "{%0,%1,%2,%3}, {%4,%5,%6,%7}, {%8,%9}, {%0,%1,%2,%3};"
        : "+f"(c[0]), "+f"(c[1]), "+f"(c[2]), "+f"(c[3])
        : "r"(a[0]), "r"(a[1]), "r"(a[2]), "r"(a[3]), "r"(b[0]), "r"(b[1]));
}
__device__ __forceinline__ uint32_t pack_bf16(float a, float b) {
    __nv_bfloat162 t = __floats2bfloat162_rn(a, b);
    return *(uint32_t*)&t;
}
__device__ __forceinline__ void split_pack(float a, float b, uint32_t& hi, uint32_t& lo) {
    __nv_bfloat16 ah = __float2bfloat16_rn(a);
    __nv_bfloat16 bh = __float2bfloat16_rn(b);
    float al = a - __bfloat162float(ah);
    float bl = b - __bfloat162float(bh);
    __nv_bfloat162 th; th.x = ah; th.y = bh;
    hi = *(uint32_t*)&th;
    lo = pack_bf16(al, bl);
}

// ---------------- split / transpose-split kernels ---------------------------
__global__ __launch_bounds__(256) void split_kernel(
    const float4* __restrict__ in, __nv_bfloat16* __restrict__ hi,
    __nv_bfloat16* __restrict__ lo, int n4)
{
    int i = blockIdx.x * blockDim.x + threadIdx.x;
    if (i >= n4) return;
    float4 v = in[i];
    float f[4] = {v.x, v.y, v.z, v.w};
    __nv_bfloat162 h2[2], l2[2];
    #pragma unroll
    for (int j = 0; j < 4; j++) {
        __nv_bfloat16 h = __float2bfloat16_rn(f[j]);
        __nv_bfloat16 l = __float2bfloat16_rn(f[j] - __bfloat162float(h));
        ((__nv_bfloat16*)h2)[j] = h;
        ((__nv_bfloat16*)l2)[j] = l;
    }
    ((__nv_bfloat162*)hi)[2 * i + 0] = h2[0];
    ((__nv_bfloat162*)hi)[2 * i + 1] = h2[1];
    ((__nv_bfloat162*)lo)[2 * i + 0] = l2[0];
    ((__nv_bfloat162*)lo)[2 * i + 1] = l2[1];
}

// W[K,N] fp32 -> Th/Tl [N,K] bf16
__global__ __launch_bounds__(256) void transpose_split_kernel(
    const float* __restrict__ W, __nv_bfloat16* __restrict__ Th,
    __nv_bfloat16* __restrict__ Tl)
{
    __shared__ float t[32][33];
    const int tx = threadIdx.x, ty = threadIdx.y;
    const int bx = blockIdx.x * 32, by = blockIdx.y * 32;
    #pragma unroll
    for (int s = 0; s < 4; s++)
        t[ty + s * 8][tx] = W[(size_t)(by + ty + s * 8) * DIM + bx + tx];
    __syncthreads();
    #pragma unroll
    for (int s = 0; s < 4; s++) {
        float v = t[tx][ty + s * 8];
        __nv_bfloat16 h = __float2bfloat16_rn(v);
        __nv_bfloat16 l = __float2bfloat16_rn(v - __bfloat162float(h));
        size_t o = (size_t)(bx + ty + s * 8) * DIM + by + tx;
        Th[o] = h; Tl[o] = l;
    }
}

// ---------------- mma.sync bf16-split GEMM: C = A@W + bias -----------------
#define GS       72
#define GTILE_B  (128 * GS * 2)
#define GBUF_B   (2 * GTILE_B)
#define GEMM_SMEM (2 * GBUF_B)

__global__ __launch_bounds__(256, 1)
void gemm_mma_kernel(const __nv_bfloat16* __restrict__ Ah,
                     const __nv_bfloat16* __restrict__ Al,
                     const __nv_bfloat16* __restrict__ Bh,
                     const __nv_bfloat16* __restrict__ Bl,
                     const float* __restrict__ bias, float* __restrict__ C)
{
    extern __shared__ char smem[];
    const uint32_t sbase = smem_u32(smem);

    const int tid  = threadIdx.x;
    const int wid  = tid >> 5;
    const int lane = tid & 31;
    const int blockRow = blockIdx.y * 128;
    const int blockCol = blockIdx.x * 128;
    const int wrow = (wid >> 2) * 64;
    const int wcol = (wid & 3) * 32;

    float acc[4][4][4];
    #pragma unroll
    for (int mi = 0; mi < 4; mi++)
        #pragma unroll
        for (int ni = 0; ni < 4; ni++)
            #pragma unroll
            for (int j = 0; j < 4; j++) acc[mi][ni][j] = 0.f;

    #define CHUNK_SRC(c, Asrc, Bsrc, koff) { \
        int ph = (c) >> 4; koff = ((c) & 15) * 64; \
        Asrc = (ph == 2) ? Al : Ah; \
        Bsrc = (ph == 1) ? Bl : Bh; }

    #define ISSUE_CHUNK(c, buf) { \
        const __nv_bfloat16 *As_, *Bs_; int ko_; \
        CHUNK_SRC(c, As_, Bs_, ko_); \
        uint32_t s0 = sbase + (buf) * GBUF_B; \
        _Pragma("unroll") \
        for (int i = 0; i < 4; i++) { \
            int idx = tid + i * 256; \
            int row = idx >> 3, seg = idx & 7; \
            cp_async16(s0 + row * 144 + seg * 16, \
                       As_ + (size_t)(blockRow + row) * DIM + ko_ + seg * 8); \
            cp_async16(s0 + GTILE_B + row * 144 + seg * 16, \
                       Bs_ + (size_t)(blockCol + row) * DIM + ko_ + seg * 8); \
        } }

    const int aRow = wrow + (lane & 15);
    const int aCol = (lane >> 4) * 8;
    const int bRow = wcol + (lane >> 4) * 8 + (lane & 7);
    const int bCol = ((lane >> 3) & 1) * 8;

    ISSUE_CHUNK(0, 0);
    cp_commit();

    for (int c = 0; c < 48; c++) {
        if (c + 1 < 48) { ISSUE_CHUNK(c + 1, (c + 1) & 1); }
        cp_commit();
        if (c + 1 < 48) cp_wait<1>(); else cp_wait<0>();
        __syncthreads();

        const uint32_t s0 = sbase + (c & 1) * GBUF_B;
        #pragma unroll
        for (int kk = 0; kk < 4; kk++) {
            uint32_t a[4][4], b[2][4];
            #pragma unroll
            for (int mi = 0; mi < 4; mi++)
                ldsm4(a[mi], s0 + ((aRow + mi * 16) * GS + kk * 16 + aCol) * 2);
            #pragma unroll
            for (int np = 0; np < 2; np++)
                ldsm4(b[np], s0 + GTILE_B +
                      ((bRow + np * 16) * GS + kk * 16 + bCol) * 2);
            #pragma unroll
            for (int mi = 0; mi < 4; mi++)
                #pragma unroll
                for (int ni = 0; ni < 4; ni++)
                    mma16816(acc[mi][ni], a[mi], &b[ni >> 1][(ni & 1) * 2]);
        }
        __syncthreads();
    }

    #pragma unroll
    for (int mi = 0; mi < 4; mi++) {
        const int r0 = blockRow + wrow + mi * 16 + (lane >> 2);
        #pragma unroll
        for (int ni = 0; ni < 4; ni++) {
            const int c0 = blockCol + wcol + ni * 8 + 2 * (lane & 3);
            float2 bv = *(const float2*)(bias + c0);
            float2 v0 = { acc[mi][ni][0] + bv.x, acc[mi][ni][1] + bv.y };
            float2 v1 = { acc[mi][ni][2] + bv.x, acc[mi][ni][3] + bv.y };
            *(float2*)(C + (size_t)r0 * DIM + c0)       = v0;
            *(float2*)(C + (size_t)(r0 + 8) * DIM + c0) = v1;
        }
    }
}

// ---------------- Flash attention with mma.sync (bf16-split, causal) -------
// Br=128 q-rows per CTA (4 warps x 32), Bc=64 keys/iter, HD=64.
// S = Qh*Kh + Qh*Kl + Ql*Kh ; P kept in registers; PV = Ph*Vh + Ph*Vl + Pl*Vh.
#define FQS 72
#define FLASH_SMEM ((2 * 128 * FQS + 4 * 64 * FQS) * 2)   // 73728 bytes

__global__ __launch_bounds__(128) void flash_mma_kernel(
    const float* __restrict__ Q, const float* __restrict__ K,
    const float* __restrict__ V, float* __restrict__ O)
{
    const int qt   = blockIdx.x;          // 0..15 (128 q rows each)
    const int bh   = blockIdx.y;          // 0..31
    const int b    = bh >> 4;
    const int h    = bh & 15;
    const int tid  = threadIdx.x;
    const int wid  = tid >> 5;
    const int lane = tid & 31;
    const int wrow = wid * 32;
    const int qbase = qt * 128;
    const size_t head_off = ((size_t)b * SEQ) * DIM + (size_t)h * HD;

    extern __shared__ __nv_bfloat16 fsm[];
    __nv_bfloat16* Qh  = fsm;                 // [128][FQS]
    __nv_bfloat16* Ql  = Qh  + 128 * FQS;
    __nv_bfloat16* Kh  = Ql  + 128 * FQS;     // [64][FQS]
    __nv_bfloat16* Kl  = Kh  + 64 * FQS;
    __nv_bfloat16* VhT = Kl  + 64 * FQS;      // [64 d][FQS keys]
    __nv_bfloat16* VlT = VhT + 64 * FQS;

    const uint32_t uQh  = smem_u32(Qh);
    const uint32_t uQl  = smem_u32(Ql);
    const uint32_t uKh  = smem_u32(Kh);
    const uint32_t uKl  = smem_u32(Kl);
    const uint32_t uVhT = smem_u32(VhT);
    const uint32_t uVlT = smem_u32(VlT);

    // ---- load Q (scaled by 1/sqrt(64)), hi/lo split ----
    #pragma unroll
    for (int i = 0; i < 16; i++) {
        int idx = tid + i * 128;
        int r = idx >> 4, c4 = (idx & 15) << 2;
        float4 v = *(const float4*)(Q + head_off + (size_t)(qbase + r) * DIM + c4);
        float f0 = v.x * 0.125f, f1 = v.y * 0.125f, f2 = v.z * 0.125f, f3 = v.w * 0.125f;
        uint32_t h01, l01, h23, l23;
        split_pack(f0, f1, h01, l01);
        split_pack(f2, f3, h23, l23);
        *(uint32_t*)&Qh[r * FQS + c4]     = h01;
        *(uint32_t*)&Qh[r * FQS + c4 + 2] = h23;
        *(uint32_t*)&Ql[r * FQS + c4]     = l01;
        *(uint32_t*)&Ql[r * FQS + c4 + 2] = l23;
    }

    float sa[2][8][4];
    float oa[2][8][4];
    float m[4], l[4];
    #pragma unroll
    for (int mi = 0; mi < 2; mi++)
        #pragma unroll
        for (int ni = 0; ni < 8; ni++)
            #pragma unroll
            for (int j = 0; j < 4; j++) oa[mi][ni][j] = 0.f;
    #pragma unroll
    for (int i = 0; i < 4; i++) { m[i] = -INFINITY; l[i] = 0.f; }

    const int nkt = 2 * qt + 2;
    for (int kt = 0; kt < nkt; kt++) {
        const int kbase = kt * 64;
        __syncthreads();  // protect prior-iter smem consumers (covers Q on iter 0)

        // ---- load K (row-major) and V (transposed), hi/lo split ----
        #pragma unroll
        for (int i = 0; i < 8; i++) {
            int idx = tid + i * 128;
            int r = idx >> 4, c4 = (idx & 15) << 2;
            float4 kv = *(const float4*)(K + head_off + (size_t)(kbase + r) * DIM + c4);
            uint32_t h01, l01, h23, l23;
            split_pack(kv.x, kv.y, h01, l01);
            split_pack(kv.z, kv.w, h23, l23);
            *(uint32_t*)&Kh[r * FQS + c4]     = h01;
            *(uint32_t*)&Kh[r * FQS + c4 + 2] = h23;
            *(uint32_t*)&Kl[r * FQS + c4]     = l01;
            *(uint32_t*)&Kl[r * FQS + c4 + 2] = l23;

            float4 vv = *(const float4*)(V + head_off + (size_t)(kbase + r) * DIM + c4);
            float vf[4] = {vv.x, vv.y, vv.z, vv.w};
            #pragma unroll
            for (int j = 0; j < 4; j++) {
                __nv_bfloat16 hi = __float2bfloat16_rn(vf[j]);
                __nv_bfloat16 lo = __float2bfloat16_rn(vf[j] - __bfloat162float(hi));
                VhT[(c4 + j) * FQS + r] = hi;
                VlT[(c4 + j) * FQS + r] = lo;
            }
        }
        __syncthreads();

        // ---- S = Q @ K^T (3-product split) ----
        #pragma unroll
        for (int mi = 0; mi < 2; mi++)
            #pragma unroll
            for (int ni = 0; ni < 8; ni++)
                #pragma unroll
                for (int j = 0; j < 4; j++) sa[mi][ni][j] = 0.f;

        #pragma unroll
        for (int kk = 0; kk < 4; kk++) {
            uint32_t aqh[2][4], aql[2][4];
            #pragma unroll
            for (int mi = 0; mi < 2; mi++) {
                uint32_t ao = ((wrow + mi * 16 + (lane & 15)) * FQS +
                               kk * 16 + (lane >> 4) * 8) * 2;
                ldsm4(aqh[mi], uQh + ao);
                ldsm4(aql[mi], uQl + ao);
            }
            #pragma unroll
            for (int g = 0; g < 4; g++) {
                uint32_t bh_[4], bl_[4];
                uint32_t bo = ((g * 16 + (lane >> 4) * 8 + (lane & 7)) * FQS +
                               kk * 16 + ((lane >> 3) & 1) * 8) * 2;
                ldsm4(bh_, uKh + bo);
                ldsm4(bl_, uKl + bo);
                #pragma unroll
                for (int mi = 0; mi < 2; mi++)
                    #pragma unroll
                    for (int p = 0; p < 2; p++) {
                        int ni = g * 2 + p;
                        mma16816(sa[mi][ni], aqh[mi], &bh_[p * 2]);
                        mma16816(sa[mi][ni], aqh[mi], &bl_[p * 2]);
                        mma16816(sa[mi][ni], aql[mi], &bh_[p * 2]);
                    }
            }
        }

        // ---- causal mask (only near-diagonal tiles) ----
        if (kbase + 63 > qbase + wrow) {
            #pragma unroll
            for (int mi = 0; mi < 2; mi++)
                #pragma unroll
                for (int ni = 0; ni < 8; ni++)
                    #pragma unroll
                    for (int j = 0; j < 4; j++) {
                        int qrow = qbase + wrow + mi * 16 + (lane >> 2) + (j >> 1) * 8;
                        int kcol = kbase + ni * 8 + 2 * (lane & 3) + (j & 1);
                        if (kcol > qrow) sa[mi][ni][j] = -INFINITY;
                    }
        }

        // ---- online softmax-one update ----
        #pragma unroll
        for (int mi = 0; mi < 2; mi++)
            #pragma unroll
            for (int rh = 0; rh < 2; rh++) {
                const int ri = mi * 2 + rh;
                float rmax = -INFINITY;
                #pragma unroll
                for (int ni = 0; ni < 8; ni++)
                    rmax = fmaxf(rmax, fmaxf(sa[mi][ni][rh * 2], sa[mi][ni][rh * 2 + 1]));
                rmax = fmaxf(rmax, __shfl_xor_sync(0xffffffffu, rmax, 1));
                rmax = fmaxf(rmax, __shfl_xor_sync(0xffffffffu, rmax, 2));
                float mnew = fmaxf(m[ri], rmax);
                float corr = __expf(m[ri] - mnew);
                float sum = 0.f;
                #pragma unroll
                for (int ni = 0; ni < 8; ni++)
                    #pragma unroll
                    for (int j2 = 0; j2 < 2; j2++) {
                        float p = __expf(sa[mi][ni][rh * 2 + j2] - mnew);
                        sa[mi][ni][rh * 2 + j2] = p;
                        sum += p;
                    }
                sum += __shfl_xor_sync(0xffffffffu, sum, 1);
                sum += __shfl_xor_sync(0xffffffffu, sum, 2);
                l[ri] = l[ri] * corr + sum;
                m[ri] = mnew;
                #pragma unroll
                for (int ni = 0; ni < 8; ni++)
                    #pragma unroll
                    for (int j2 = 0; j2 < 2; j2++)
                        oa[mi][ni][rh * 2 + j2] *= corr;
            }

        // ---- O += P @ V (P from registers, 3-product split) ----
        #pragma unroll
        for (int kk = 0; kk < 4; kk++) {
            uint32_t ph[2][4], pl[2][4];
            #pragma unroll
            for (int mi = 0; mi < 2; mi++) {
                split_pack(sa[mi][2 * kk][0],     sa[mi][2 * kk][1],     ph[mi][0], pl[mi][0]);
                split_pack(sa[mi][2 * kk][2],     sa[mi][2 * kk][3],     ph[mi][1], pl[mi][1]);
                split_pack(sa[mi][2 * kk + 1][0], sa[mi][2 * kk + 1][1], ph[mi][2], pl[mi][2]);
                split_pack(sa[mi][2 * kk + 1][2], sa[mi][2 * kk + 1][3], ph[mi][3], pl[mi][3]);
            }
            #pragma unroll
            for (int dg = 0; dg < 4; dg++) {
                uint32_t bvh[4], bvl[4];
                uint32_t bo = ((dg * 16 + (lane >> 4) * 8 + (lane & 7)) * FQS +
                               kk * 16 + ((lane >> 3) & 1) * 8) * 2;
                ldsm4(bvh, uVhT + bo);
                ldsm4(bvl, uVlT + bo);
                #pragma unroll
                for (int mi = 0; mi < 2; mi++)
                    #pragma unroll
                    for (int p = 0; p < 2; p++) {
                        int ni = dg * 2 + p;
                        mma16816(oa[mi][ni], ph[mi], &bvh[p * 2]);
                        mma16816(oa[mi][ni], ph[mi], &bvl[p * 2]);
                        mma16816(oa[mi][ni], pl[mi], &bvh[p * 2]);
                    }
            }
        }
    }

    // ---- epilogue: divide by (1 + l), store fp32 ----
    #pragma unroll
    for (int mi = 0; mi < 2; mi++) {
        const float inv0 = 1.f / (1.f + l[mi * 2 + 0]);
        const float inv1 = 1.f / (1.f + l[mi * 2 + 1]);
        const int r0 = qbase + wrow + mi * 16 + (lane >> 2);
        #pragma unroll
        for (int ni = 0; ni < 8; ni++) {
            const int c0 = ni * 8 + 2 * (lane & 3);
            float2 v0 = { oa[mi][ni][0] * inv0, oa[mi][ni][1] * inv0 };
            float2 v1 = { oa[mi][ni][2] * inv1, oa[mi][ni][3] * inv1 };
            *(float2*)(O + head_off + (size_t)r0 * DIM + c0)       = v0;
            *(float2*)(O + head_off + (size_t)(r0 + 8) * DIM + c0) = v1;
        }
    }
}

// ---------------- launcher -------------------------------------------------
extern "C" void kernel_launch(void* const* d_in, const int* in_sizes, int n_in,
                              void* d_out, int out_size)
{
    const float* x  = (const float*)d_in[0];
    const float* Wq = (const float*)d_in[1];
    const float* bq = (const float*)d_in[2];
    const float* Wk = (const float*)d_in[3];
    const float* bk = (const float*)d_in[4];
    const float* Wv = (const float*)d_in[5];
    const float* bv = (const float*)d_in[6];
    const float* Wo = (const float*)d_in[7];
    const float* bo = (const float*)d_in[8];
    float* out = (float*)d_out;

    float *q, *k, *v, *ctx;
    __nv_bfloat16 *xh, *xl, *wth, *wtl;
    cudaGetSymbolAddress((void**)&q,   g_q);
    cudaGetSymbolAddress((void**)&k,   g_k);
    cudaGetSymbolAddress((void**)&v,   g_v);
    cudaGetSymbolAddress((void**)&ctx, g_ctx);
    cudaGetSymbolAddress((void**)&xh,  g_xh);
    cudaGetSymbolAddress((void**)&xl,  g_xl);
    cudaGetSymbolAddress((void**)&wth, g_wth);
    cudaGetSymbolAddress((void**)&wtl, g_wtl);

    cudaFuncSetAttribute(flash_mma_kernel,
                         cudaFuncAttributeMaxDynamicSharedMemorySize, FLASH_SMEM);
    cudaFuncSetAttribute(gemm_mma_kernel,
                         cudaFuncAttributeMaxDynamicSharedMemorySize, GEMM_SMEM);

    const int n4 = MROWS * DIM / 4;
    dim3 tb(32, 8), tg(32, 32);

    split_kernel<<<(n4 + 255) / 256, 256>>>((const float4*)x, xh, xl, n4);
    transpose_split_kernel<<<tg, tb>>>(Wq, wth + 0 * DIM * DIM, wtl + 0 * DIM * DIM);
    transpose_split_kernel<<<tg, tb>>>(Wk, wth + 1 * DIM * DIM, wtl + 1 * DIM * DIM);
    transpose_split_kernel<<<tg, tb>>>(Wv, wth + 2 * DIM * DIM, wtl + 2 * DIM * DIM);
    transpose_split_kernel<<<tg, tb>>>(Wo, wth + 3 * DIM * DIM, wtl + 3 * DIM * DIM);

    dim3 gg(DIM / 128, MROWS / 128);   // (8, 32)
    gemm_mma_kernel<<<gg, 256, GEMM_SMEM>>>(xh, xl, wth + 0 * DIM * DIM, wtl + 0 * DIM * DIM, bq, q);
    gemm_mma_kernel<<<gg, 256, GEMM_SMEM>>>(xh, xl, wth + 1 * DIM * DIM, wtl + 1 * DIM * DIM, bk, k);
    gemm_mma_kernel<<<gg, 256, GEMM_SMEM>>>(xh, xl, wth + 2 * DIM * DIM, wtl + 2 * DIM * DIM, bv, v);

    dim3 attnGrid(SEQ / 128, BATCH * NHEAD);   // (16, 32)
    flash_mma_kernel<<<attnGrid, 128, FLASH_SMEM>>>(q, k, v, ctx);

    split_kernel<<<(n4 + 255) / 256, 256>>>((const float4*)ctx, xh, xl, n4);
    gemm_mma_kernel<<<gg, 256, GEMM_SMEM>>>(xh, xl, wth + 3 * DIM * DIM, wtl + 3 * DIM * DIM, bo, out);
}

// round 6
// speedup vs baseline: 2.7385x; 1.1471x over previous
#include <cuda_runtime.h>
#include <cuda_bf16.h>
#include <math.h>
#include <stdint.h>

#define BATCH 2
#define SEQ   2048
#define DIM   1024
#define NHEAD 16
#define HD    64
#define MROWS (BATCH * SEQ)   // 4096
#define NQKV  (3 * DIM)       // 3072

// ---------------- scratch (device globals; no runtime allocation) ----------
__device__ __nv_bfloat16 g_xh[MROWS * DIM];
__device__ __nv_bfloat16 g_xl[MROWS * DIM];
__device__ __nv_bfloat16 g_wth[4 * DIM * DIM];
__device__ __nv_bfloat16 g_wtl[4 * DIM * DIM];
__device__ __nv_bfloat16 g_qkvh[MROWS * NQKV];
__device__ __nv_bfloat16 g_qkvl[MROWS * NQKV];

// ---------------- PTX helpers (sm_80-era only; no 'a'-gated features) ------
__device__ __forceinline__ uint32_t smem_u32(const void* p) {
    uint32_t a;
    asm("{ .reg .u64 t; cvta.to.shared.u64 t, %1; cvt.u32.u64 %0, t; }"
        : "=r"(a) : "l"(p));
    return a;
}
__device__ __forceinline__ void cp_async16(uint32_t saddr, const void* gptr) {
    asm volatile("cp.async.cg.shared.global [%0], [%1], 16;"
                 :: "r"(saddr), "l"(gptr));
}
__device__ __forceinline__ void cp_commit() {
    asm volatile("cp.async.commit_group;");
}
template <int N>
__device__ __forceinline__ void cp_wait() {
    asm volatile("cp.async.wait_group %0;" :: "n"(N));
}
__device__ __forceinline__ void ldsm4(uint32_t* r, uint32_t addr) {
    asm volatile("ldmatrix.sync.aligned.m8n8.x4.shared.b16 {%0,%1,%2,%3}, [%4];"
                 : "=r"(r[0]), "=r"(r[1]), "=r"(r[2]), "=r"(r[3]) : "r"(addr));
}
__device__ __forceinline__ void ldsm4t(uint32_t* r, uint32_t addr) {
    asm volatile("ldmatrix.sync.aligned.m8n8.x4.trans.shared.b16 {%0,%1,%2,%3}, [%4];"
                 : "=r"(r[0]), "=r"(r[1]), "=r"(r[2]), "=r"(r[3]) : "r"(addr));
}
__device__ __forceinline__ void mma16816(float* c, const uint32_t* a, const uint32_t* b) {
    asm volatile(
        "mma.sync.aligned.m16n8k16.row.col.f32.bf16.bf16.f32 "
        "{%0,%1,%2,%3}, {%4,%5,%6,%7}, {%8,%9}, {%0,%1,%2,%3};"
        : "+f"(c[0]), "+f"(c[1]), "+f"(c[2]), "+f"(c[3])
        : "r"(a[0]), "r"(a[1]), "r"(a[2]), "r"(a[3]), "r"(b[0]), "r"(b[1]));
}
__device__ __forceinline__ uint32_t pack_bf16(float a, float b) {
    __nv_bfloat162 t = __floats2bfloat162_rn(a, b);
    return *(uint32_t*)&t;
}
__device__ __forceinline__ void split_pack(float a, float b, uint32_t& hi, uint32_t& lo) {
    __nv_bfloat16 ah = __float2bfloat16_rn(a);
    __nv_bfloat16 bh = __float2bfloat16_rn(b);
    float al = a - __bfloat162float(ah);
    float bl = b - __bfloat162float(bh);
    __nv_bfloat162 th; th.x = ah; th.y = bh;
    hi = *(uint32_t*)&th;
    lo = pack_bf16(al, bl);
}

// ---------------- split / transpose-split kernels ---------------------------
__global__ __launch_bounds__(256) void split_kernel(
    const float4* __restrict__ in, __nv_bfloat16* __restrict__ hi,
    __nv_bfloat16* __restrict__ lo, int n4)
{
    int i = blockIdx.x * blockDim.x + threadIdx.x;
    if (i >= n4) return;
    float4 v = in[i];
    float f[4] = {v.x, v.y, v.z, v.w};
    __nv_bfloat162 h2[2], l2[2];
    #pragma unroll
    for (int j = 0; j < 4; j++) {
        __nv_bfloat16 h = __float2bfloat16_rn(f[j]);
        __nv_bfloat16 l = __float2bfloat16_rn(f[j] - __bfloat162float(h));
        ((__nv_bfloat16*)h2)[j] = h;
        ((__nv_bfloat16*)l2)[j] = l;
    }
    ((__nv_bfloat162*)hi)[2 * i + 0] = h2[0];
    ((__nv_bfloat162*)hi)[2 * i + 1] = h2[1];
    ((__nv_bfloat162*)lo)[2 * i + 0] = l2[0];
    ((__nv_bfloat162*)lo)[2 * i + 1] = l2[1];
}

// W[K,N] fp32 -> Th/Tl [N,K] bf16
__global__ __launch_bounds__(256) void transpose_split_kernel(
    const float* __restrict__ W, __nv_bfloat16* __restrict__ Th,
    __nv_bfloat16* __restrict__ Tl)
{
    __shared__ float t[32][33];
    const int tx = threadIdx.x, ty = threadIdx.y;
    const int bx = blockIdx.x * 32, by = blockIdx.y * 32;
    #pragma unroll
    for (int s = 0; s < 4; s++)
        t[ty + s * 8][tx] = W[(size_t)(by + ty + s * 8) * DIM + bx + tx];
    __syncthreads();
    #pragma unroll
    for (int s = 0; s < 4; s++) {
        float v = t[tx][ty + s * 8];
        __nv_bfloat16 h = __float2bfloat16_rn(v);
        __nv_bfloat16 l = __float2bfloat16_rn(v - __bfloat162float(h));
        size_t o = (size_t)(bx + ty + s * 8) * DIM + by + tx;
        Th[o] = h; Tl[o] = l;
    }
}

// ---------------- shared GEMM plumbing -------------------------------------
#define GS       72
#define GTILE_B  (128 * GS * 2)
#define GBUF_B   (2 * GTILE_B)
#define GEMM_SMEM (2 * GBUF_B)

#define CHUNK_SRC(c, Asrc, Bsrc, koff) { \
    int ph = (c) >> 4; koff = ((c) & 15) * 64; \
    Asrc = (ph == 2) ? Al : Ah; \
    Bsrc = (ph == 1) ? Bl : Bh; }

#define ISSUE_CHUNK(c, buf, bRowBase) { \
    const __nv_bfloat16 *As_, *Bs_; int ko_; \
    CHUNK_SRC(c, As_, Bs_, ko_); \
    uint32_t s0 = sbase + (buf) * GBUF_B; \
    _Pragma("unroll") \
    for (int i = 0; i < 4; i++) { \
        int idx = tid + i * 256; \
        int row = idx >> 3, seg = idx & 7; \
        cp_async16(s0 + row * 144 + seg * 16, \
                   As_ + (size_t)(blockRow + row) * DIM + ko_ + seg * 8); \
        cp_async16(s0 + GTILE_B + row * 144 + seg * 16, \
                   Bs_ + (size_t)((bRowBase) + row) * DIM + ko_ + seg * 8); \
    } }

#define GEMM_MAINLOOP() \
    ISSUE_CHUNK(0, 0, blockCol); \
    cp_commit(); \
    for (int c = 0; c < 48; c++) { \
        if (c + 1 < 48) { ISSUE_CHUNK(c + 1, (c + 1) & 1, blockCol); } \
        cp_commit(); \
        if (c + 1 < 48) cp_wait<1>(); else cp_wait<0>(); \
        __syncthreads(); \
        const uint32_t s0 = sbase + (c & 1) * GBUF_B; \
        _Pragma("unroll") \
        for (int kk = 0; kk < 4; kk++) { \
            uint32_t a[4][4], b[2][4]; \
            _Pragma("unroll") \
            for (int mi = 0; mi < 4; mi++) \
                ldsm4(a[mi], s0 + ((aRow + mi * 16) * GS + kk * 16 + aCol) * 2); \
            _Pragma("unroll") \
            for (int np = 0; np < 2; np++) \
                ldsm4(b[np], s0 + GTILE_B + \
                      ((bRow + np * 16) * GS + kk * 16 + bCol) * 2); \
            _Pragma("unroll") \
            for (int mi = 0; mi < 4; mi++) \
                _Pragma("unroll") \
                for (int ni = 0; ni < 4; ni++) \
                    mma16816(acc[mi][ni], a[mi], &b[ni >> 1][(ni & 1) * 2]); \
        } \
        __syncthreads(); \
    }

// ---------------- fused QKV GEMM: writes bf16 hi/lo, Q scaled by 0.125 -----
__global__ __launch_bounds__(256, 1)
void gemm_qkv_kernel(const __nv_bfloat16* __restrict__ Ah,
                     const __nv_bfloat16* __restrict__ Al,
                     const __nv_bfloat16* __restrict__ Bh,
                     const __nv_bfloat16* __restrict__ Bl,
                     const float* __restrict__ bq,
                     const float* __restrict__ bk,
                     const float* __restrict__ bv,
                     __nv_bfloat16* __restrict__ Ch,
                     __nv_bfloat16* __restrict__ Cl)
{
    extern __shared__ char smem[];
    const uint32_t sbase = smem_u32(smem);
    const int tid  = threadIdx.x;
    const int wid  = tid >> 5;
    const int lane = tid & 31;
    const int blockRow = blockIdx.y * 128;
    const int blockCol = blockIdx.x * 128;      // 0..2944
    const int wrow = (wid >> 2) * 64;
    const int wcol = (wid & 3) * 32;

    const float scale = (blockCol < DIM) ? 0.125f : 1.0f;
    const float* bsel;
    int cb;
    if (blockCol < DIM)            { bsel = bq; cb = blockCol; }
    else if (blockCol < 2 * DIM)   { bsel = bk; cb = blockCol - DIM; }
    else                           { bsel = bv; cb = blockCol - 2 * DIM; }

    float acc[4][4][4];
    #pragma unroll
    for (int mi = 0; mi < 4; mi++)
        #pragma unroll
        for (int ni = 0; ni < 4; ni++)
            #pragma unroll
            for (int j = 0; j < 4; j++) acc[mi][ni][j] = 0.f;

    const int aRow = wrow + (lane & 15);
    const int aCol = (lane >> 4) * 8;
    const int bRow = wcol + (lane >> 4) * 8 + (lane & 7);
    const int bCol = ((lane >> 3) & 1) * 8;

    GEMM_MAINLOOP();

    #pragma unroll
    for (int mi = 0; mi < 4; mi++) {
        const int r0 = blockRow + wrow + mi * 16 + (lane >> 2);
        #pragma unroll
        for (int ni = 0; ni < 4; ni++) {
            const int cc = wcol + ni * 8 + 2 * (lane & 3);
            float2 bv2 = *(const float2*)(bsel + cb + cc);
            const int gc = blockCol + cc;
            float v0x = (acc[mi][ni][0] + bv2.x) * scale;
            float v0y = (acc[mi][ni][1] + bv2.y) * scale;
            float v1x = (acc[mi][ni][2] + bv2.x) * scale;
            float v1y = (acc[mi][ni][3] + bv2.y) * scale;
            uint32_t h0, l0, h1, l1;
            split_pack(v0x, v0y, h0, l0);
            split_pack(v1x, v1y, h1, l1);
            *(uint32_t*)(Ch + (size_t)r0 * NQKV + gc)       = h0;
            *(uint32_t*)(Cl + (size_t)r0 * NQKV + gc)       = l0;
            *(uint32_t*)(Ch + (size_t)(r0 + 8) * NQKV + gc) = h1;
            *(uint32_t*)(Cl + (size_t)(r0 + 8) * NQKV + gc) = l1;
        }
    }
}

// ---------------- O-projection GEMM: fp32 out + bias -----------------------
__global__ __launch_bounds__(256, 1)
void gemm_mma_kernel(const __nv_bfloat16* __restrict__ Ah,
                     const __nv_bfloat16* __restrict__ Al,
                     const __nv_bfloat16* __restrict__ Bh,
                     const __nv_bfloat16* __restrict__ Bl,
                     const float* __restrict__ bias, float* __restrict__ C)
{
    extern __shared__ char smem[];
    const uint32_t sbase = smem_u32(smem);
    const int tid  = threadIdx.x;
    const int wid  = tid >> 5;
    const int lane = tid & 31;
    const int blockRow = blockIdx.y * 128;
    const int blockCol = blockIdx.x * 128;
    const int wrow = (wid >> 2) * 64;
    const int wcol = (wid & 3) * 32;

    float acc[4][4][4];
    #pragma unroll
    for (int mi = 0; mi < 4; mi++)
        #pragma unroll
        for (int ni = 0; ni < 4; ni++)
            #pragma unroll
            for (int j = 0; j < 4; j++) acc[mi][ni][j] = 0.f;

    const int aRow = wrow + (lane & 15);
    const int aCol = (lane >> 4) * 8;
    const int bRow = wcol + (lane >> 4) * 8 + (lane & 7);
    const int bCol = ((lane >> 3) & 1) * 8;

    GEMM_MAINLOOP();

    #pragma unroll
    for (int mi = 0; mi < 4; mi++) {
        const int r0 = blockRow + wrow + mi * 16 + (lane >> 2);
        #pragma unroll
        for (int ni = 0; ni < 4; ni++) {
            const int c0 = blockCol + wcol + ni * 8 + 2 * (lane & 3);
            float2 bv = *(const float2*)(bias + c0);
            float2 v0 = { acc[mi][ni][0] + bv.x, acc[mi][ni][1] + bv.y };
            float2 v1 = { acc[mi][ni][2] + bv.x, acc[mi][ni][3] + bv.y };
            *(float2*)(C + (size_t)r0 * DIM + c0)       = v0;
            *(float2*)(C + (size_t)(r0 + 8) * DIM + c0) = v1;
        }
    }
}

// ---------------- Flash attention (bf16-split mma, causal, softmax-one) ----
// Inputs: packed QKV hi/lo bf16 [4096][3072] (Q pre-scaled).
// Br=128 (4 warps x 32 rows), Bc=64, HD=64. Each CTA does q-tiles {x, 15-x}.
// V kept row-major; PV B-fragments via ldmatrix.trans.
#define FQS 72
#define FQ_ELE   (128 * FQS)                 // Q tile elems (per hi/lo)
#define FKV_ELE  (64 * FQS)                  // per K/V array
#define FKVBUF   (4 * FKV_ELE)               // Kh,Kl,Vh,Vl
#define FLASH_SMEM ((2 * FQ_ELE + 2 * FKVBUF) * 2)   // 110592 bytes

__global__ __launch_bounds__(128) void flash_mma_kernel(
    const __nv_bfloat16* __restrict__ QKVh,
    const __nv_bfloat16* __restrict__ QKVl,
    __nv_bfloat16* __restrict__ Ch,
    __nv_bfloat16* __restrict__ Cl)
{
    const int bx   = blockIdx.x;          // 0..7
    const int bh   = blockIdx.y;          // 0..31
    const int b    = bh >> 4;
    const int h    = bh & 15;
    const int tid  = threadIdx.x;
    const int wid  = tid >> 5;
    const int lane = tid & 31;
    const int wrow = wid * 32;
    const size_t rowbase = (size_t)b * SEQ;          // token row base
    const int qcol = h * HD;                          // Q col offset in 3072
    const int kcol = qcol + DIM;
    const int vcol = qcol + 2 * DIM;

    extern __shared__ __nv_bfloat16 fsm[];
    const uint32_t uQh = smem_u32(fsm);
    const uint32_t uQl = uQh + FQ_ELE * 2;
    const uint32_t uKV0 = uQl + FQ_ELE * 2;           // buf0: Kh,Kl,Vh,Vl
    // per-buffer offsets (bytes)
    #define KV_KH(bb) (uKV0 + (bb) * FKVBUF * 2)
    #define KV_KL(bb) (KV_KH(bb) + FKV_ELE * 2)
    #define KV_VH(bb) (KV_KH(bb) + 2 * FKV_ELE * 2)
    #define KV_VL(bb) (KV_KH(bb) + 3 * FKV_ELE * 2)

    #define ISSUE_Q(qb) { \
        _Pragma("unroll") \
        for (int i = 0; i < 8; i++) { \
            int idx = tid + i * 128; \
            int r = idx >> 3, seg = idx & 7; \
            size_t g = (rowbase + (qb) + r) * NQKV + qcol + seg * 8; \
            cp_async16(uQh + r * 144 + seg * 16, QKVh + g); \
            cp_async16(uQl + r * 144 + seg * 16, QKVl + g); \
        } }

    #define ISSUE_KV(kb, bb) { \
        _Pragma("unroll") \
        for (int i = 0; i < 4; i++) { \
            int idx = tid + i * 128; \
            int r = idx >> 3, seg = idx & 7; \
            size_t gk = (rowbase + (kb) + r) * NQKV + kcol + seg * 8; \
            size_t gv = (rowbase + (kb) + r) * NQKV + vcol + seg * 8; \
            uint32_t so = r * 144 + seg * 16; \
            cp_async16(KV_KH(bb) + so, QKVh + gk); \
            cp_async16(KV_KL(bb) + so, QKVl + gk); \
            cp_async16(KV_VH(bb) + so, QKVh + gv); \
            cp_async16(KV_VL(bb) + so, QKVl + gv); \
        } }

    for (int t = 0; t < 2; t++) {
        const int qt = (t == 0) ? bx : (15 - bx);
        const int qbase = qt * 128;

        float sa[2][8][4];
        float oa[2][8][4];
        float m[4], l[4];
        #pragma unroll
        for (int mi = 0; mi < 2; mi++)
            #pragma unroll
            for (int ni = 0; ni < 8; ni++)
                #pragma unroll
                for (int j = 0; j < 4; j++) oa[mi][ni][j] = 0.f;
        #pragma unroll
        for (int i = 0; i < 4; i++) { m[i] = -INFINITY; l[i] = 0.f; }

        __syncthreads();          // prior tile's smem consumers done
        ISSUE_Q(qbase);
        ISSUE_KV(0, 0);
        cp_commit();

        const int nkt = 2 * qt + 2;
        for (int kt = 0; kt < nkt; kt++) {
            const int kbase = kt * 64;
            if (kt + 1 < nkt) { ISSUE_KV((kt + 1) * 64, (kt + 1) & 1); }
            cp_commit();
            if (kt + 1 < nkt) cp_wait<1>(); else cp_wait<0>();
            __syncthreads();

            const int bb = kt & 1;
            const uint32_t uKh = KV_KH(bb), uKl = KV_KL(bb);
            const uint32_t uVh = KV_VH(bb), uVl = KV_VL(bb);

            // ---- S = Q @ K^T (3-product split) ----
            #pragma unroll
            for (int mi = 0; mi < 2; mi++)
                #pragma unroll
                for (int ni = 0; ni < 8; ni++)
                    #pragma unroll
                    for (int j = 0; j < 4; j++) sa[mi][ni][j] = 0.f;

            #pragma unroll
            for (int kk = 0; kk < 4; kk++) {
                uint32_t aqh[2][4], aql[2][4];
                #pragma unroll
                for (int mi = 0; mi < 2; mi++) {
                    uint32_t ao = ((wrow + mi * 16 + (lane & 15)) * FQS +
                                   kk * 16 + (lane >> 4) * 8) * 2;
                    ldsm4(aqh[mi], uQh + ao);
                    ldsm4(aql[mi], uQl + ao);
                }
                #pragma unroll
                for (int g = 0; g < 4; g++) {
                    uint32_t bh_[4], bl_[4];
                    uint32_t bo = ((g * 16 + (lane >> 4) * 8 + (lane & 7)) * FQS +
                                   kk * 16 + ((lane >> 3) & 1) * 8) * 2;
                    ldsm4(bh_, uKh + bo);
                    ldsm4(bl_, uKl + bo);
                    #pragma unroll
                    for (int mi = 0; mi < 2; mi++)
                        #pragma unroll
                        for (int p = 0; p < 2; p++) {
                            int ni = g * 2 + p;
                            mma16816(sa[mi][ni], aqh[mi], &bh_[p * 2]);
                            mma16816(sa[mi][ni], aqh[mi], &bl_[p * 2]);
                            mma16816(sa[mi][ni], aql[mi], &bh_[p * 2]);
                        }
                }
            }

            // ---- causal mask (near-diagonal tiles only) ----
            if (kbase + 63 > qbase + wrow) {
                #pragma unroll
                for (int mi = 0; mi < 2; mi++)
                    #pragma unroll
                    for (int ni = 0; ni < 8; ni++)
                        #pragma unroll
                        for (int j = 0; j < 4; j++) {
                            int qrow = qbase + wrow + mi * 16 + (lane >> 2) + (j >> 1) * 8;
                            int kc = kbase + ni * 8 + 2 * (lane & 3) + (j & 1);
                            if (kc > qrow) sa[mi][ni][j] = -INFINITY;
                        }
            }

            // ---- online softmax-one update ----
            #pragma unroll
            for (int mi = 0; mi < 2; mi++)
                #pragma unroll
                for (int rh = 0; rh < 2; rh++) {
                    const int ri = mi * 2 + rh;
                    float rmax = -INFINITY;
                    #pragma unroll
                    for (int ni = 0; ni < 8; ni++)
                        rmax = fmaxf(rmax, fmaxf(sa[mi][ni][rh * 2], sa[mi][ni][rh * 2 + 1]));
                    rmax = fmaxf(rmax, __shfl_xor_sync(0xffffffffu, rmax, 1));
                    rmax = fmaxf(rmax, __shfl_xor_sync(0xffffffffu, rmax, 2));
                    float mnew = fmaxf(m[ri], rmax);
                    float corr = __expf(m[ri] - mnew);
                    float sum = 0.f;
                    #pragma unroll
                    for (int ni = 0; ni < 8; ni++)
                        #pragma unroll
                        for (int j2 = 0; j2 < 2; j2++) {
                            float p = __expf(sa[mi][ni][rh * 2 + j2] - mnew);
                            sa[mi][ni][rh * 2 + j2] = p;
                            sum += p;
                        }
                    sum += __shfl_xor_sync(0xffffffffu, sum, 1);
                    sum += __shfl_xor_sync(0xffffffffu, sum, 2);
                    l[ri] = l[ri] * corr + sum;
                    m[ri] = mnew;
                    #pragma unroll
                    for (int ni = 0; ni < 8; ni++)
                        #pragma unroll
                        for (int j2 = 0; j2 < 2; j2++)
                            oa[mi][ni][rh * 2 + j2] *= corr;
                }

            // ---- O += P @ V : V row-major, B-fragments via ldmatrix.trans --
            #pragma unroll
            for (int kk = 0; kk < 4; kk++) {
                uint32_t ph[2][4], pl[2][4];
                #pragma unroll
                for (int mi = 0; mi < 2; mi++) {
                    split_pack(sa[mi][2 * kk][0],     sa[mi][2 * kk][1],     ph[mi][0], pl[mi][0]);
                    split_pack(sa[mi][2 * kk][2],     sa[mi][2 * kk][3],     ph[mi][1], pl[mi][1]);
                    split_pack(sa[mi][2 * kk + 1][0], sa[mi][2 * kk + 1][1], ph[mi][2], pl[mi][2]);
                    split_pack(sa[mi][2 * kk + 1][2], sa[mi][2 * kk + 1][3], ph[mi][3], pl[mi][3]);
                }
                #pragma unroll
                for (int dg = 0; dg < 4; dg++) {
                    uint32_t bvh[4], bvl[4];
                    uint32_t bo = ((kk * 16 + ((lane >> 3) & 1) * 8 + (lane & 7)) * FQS +
                                   dg * 16 + (lane >> 4) * 8) * 2;
                    ldsm4t(bvh, uVh + bo);
                    ldsm4t(bvl, uVl + bo);
                    #pragma unroll
                    for (int mi = 0; mi < 2; mi++)
                        #pragma unroll
                        for (int p = 0; p < 2; p++) {
                            int ni = dg * 2 + p;
                            mma16816(oa[mi][ni], ph[mi], &bvh[p * 2]);
                            mma16816(oa[mi][ni], ph[mi], &bvl[p * 2]);
                            mma16816(oa[mi][ni], pl[mi], &bvh[p * 2]);
                        }
                }
            }
            __syncthreads();
        }

        // ---- epilogue: divide by (1 + l), write ctx bf16 hi/lo ----
        #pragma unroll
        for (int mi = 0; mi < 2; mi++) {
            const float inv0 = 1.f / (1.f + l[mi * 2 + 0]);
            const float inv1 = 1.f / (1.f + l[mi * 2 + 1]);
            const int r0 = qbase + wrow + mi * 16 + (lane >> 2);
            #pragma unroll
            for (int ni = 0; ni < 8; ni++) {
                const int c0 = ni * 8 + 2 * (lane & 3);
                uint32_t h0, l0, h1, l1;
                split_pack(oa[mi][ni][0] * inv0, oa[mi][ni][1] * inv0, h0, l0);
                split_pack(oa[mi][ni][2] * inv1, oa[mi][ni][3] * inv1, h1, l1);
                size_t o0 = (rowbase + r0) * DIM + qcol + c0;
                size_t o1 = (rowbase + r0 + 8) * DIM + qcol + c0;
                *(uint32_t*)(Ch + o0) = h0;
                *(uint32_t*)(Cl + o0) = l0;
                *(uint32_t*)(Ch + o1) = h1;
                *(uint32_t*)(Cl + o1) = l1;
            }
        }
    }
}

// ---------------- launcher -------------------------------------------------
extern "C" void kernel_launch(void* const* d_in, const int* in_sizes, int n_in,
                              void* d_out, int out_size)
{
    const float* x  = (const float*)d_in[0];
    const float* Wq = (const float*)d_in[1];
    const float* bq = (const float*)d_in[2];
    const float* Wk = (const float*)d_in[3];
    const float* bk = (const float*)d_in[4];
    const float* Wv = (const float*)d_in[5];
    const float* bv = (const float*)d_in[6];
    const float* Wo = (const float*)d_in[7];
    const float* bo = (const float*)d_in[8];
    float* out = (float*)d_out;

    __nv_bfloat16 *xh, *xl, *wth, *wtl, *qkvh, *qkvl;
    cudaGetSymbolAddress((void**)&xh,   g_xh);
    cudaGetSymbolAddress((void**)&xl,   g_xl);
    cudaGetSymbolAddress((void**)&wth,  g_wth);
    cudaGetSymbolAddress((void**)&wtl,  g_wtl);
    cudaGetSymbolAddress((void**)&qkvh, g_qkvh);
    cudaGetSymbolAddress((void**)&qkvl, g_qkvl);

    cudaFuncSetAttribute(flash_mma_kernel,
                         cudaFuncAttributeMaxDynamicSharedMemorySize, FLASH_SMEM);
    cudaFuncSetAttribute(gemm_qkv_kernel,
                         cudaFuncAttributeMaxDynamicSharedMemorySize, GEMM_SMEM);
    cudaFuncSetAttribute(gemm_mma_kernel,
                         cudaFuncAttributeMaxDynamicSharedMemorySize, GEMM_SMEM);

    const int n4 = MROWS * DIM / 4;
    dim3 tb(32, 8), tg(32, 32);

    split_kernel<<<(n4 + 255) / 256, 256>>>((const float4*)x, xh, xl, n4);
    transpose_split_kernel<<<tg, tb>>>(Wq, wth + 0 * DIM * DIM, wtl + 0 * DIM * DIM);
    transpose_split_kernel<<<tg, tb>>>(Wk, wth + 1 * DIM * DIM, wtl + 1 * DIM * DIM);
    transpose_split_kernel<<<tg, tb>>>(Wv, wth + 2 * DIM * DIM, wtl + 2 * DIM * DIM);
    transpose_split_kernel<<<tg, tb>>>(Wo, wth + 3 * DIM * DIM, wtl + 3 * DIM * DIM);

    dim3 gqkv(NQKV / 128, MROWS / 128);        // (24, 32)
    gemm_qkv_kernel<<<gqkv, 256, GEMM_SMEM>>>(xh, xl, wth, wtl, bq, bk, bv, qkvh, qkvl);

    dim3 attnGrid(SEQ / 256, BATCH * NHEAD);   // (8, 32), 2 q-tiles per CTA
    flash_mma_kernel<<<attnGrid, 128, FLASH_SMEM>>>(qkvh, qkvl, xh, xl);

    dim3 gо(DIM / 128, MROWS / 128);           // (8, 32)
    gemm_mma_kernel<<<gо, 256, GEMM_SMEM>>>(xh, xl, wth + 3 * DIM * DIM, wtl + 3 * DIM * DIM, bo, out);
}

// round 7
// speedup vs baseline: 2.9917x; 1.0925x over previous
#include <cuda_runtime.h>
#include <cuda_bf16.h>
#include <math.h>
#include <stdint.h>

#define BATCH 2
#define SEQ   2048
#define DIM   1024
#define NHEAD 16
#define HD    64
#define MROWS (BATCH * SEQ)   // 4096
#define NQKV  (3 * DIM)       // 3072

// ---------------- scratch (device globals; no runtime allocation) ----------
__device__ __nv_bfloat16 g_xh[MROWS * DIM];
__device__ __nv_bfloat16 g_xl[MROWS * DIM];
__device__ __nv_bfloat16 g_wth[4 * DIM * DIM];
__device__ __nv_bfloat16 g_wtl[4 * DIM * DIM];
__device__ __nv_bfloat16 g_qkvh[MROWS * NQKV];
__device__ __nv_bfloat16 g_qkvl[MROWS * NQKV];

// ---------------- PTX helpers (sm_80-era only; no 'a'-gated features) ------
__device__ __forceinline__ uint32_t smem_u32(const void* p) {
    uint32_t a;
    asm("{ .reg .u64 t; cvta.to.shared.u64 t, %1; cvt.u32.u64 %0, t; }"
        : "=r"(a) : "l"(p));
    return a;
}
__device__ __forceinline__ void cp_async16(uint32_t saddr, const void* gptr) {
    asm volatile("cp.async.cg.shared.global [%0], [%1], 16;"
                 :: "r"(saddr), "l"(gptr));
}
__device__ __forceinline__ void cp_commit() {
    asm volatile("cp.async.commit_group;");
}
template <int N>
__device__ __forceinline__ void cp_wait() {
    asm volatile("cp.async.wait_group %0;" :: "n"(N));
}
__device__ __forceinline__ void ldsm4(uint32_t* r, uint32_t addr) {
    asm volatile("ldmatrix.sync.aligned.m8n8.x4.shared.b16 {%0,%1,%2,%3}, [%4];"
                 : "=r"(r[0]), "=r"(r[1]), "=r"(r[2]), "=r"(r[3]) : "r"(addr));
}
__device__ __forceinline__ void ldsm4t(uint32_t* r, uint32_t addr) {
    asm volatile("ldmatrix.sync.aligned.m8n8.x4.trans.shared.b16 {%0,%1,%2,%3}, [%4];"
                 : "=r"(r[0]), "=r"(r[1]), "=r"(r[2]), "=r"(r[3]) : "r"(addr));
}
__device__ __forceinline__ void mma16816(float* c, const uint32_t* a, const uint32_t* b) {
    asm volatile(
        "mma.sync.aligned.m16n8k16.row.col.f32.bf16.bf16.f32 "
        "{%0,%1,%2,%3}, {%4,%5,%6,%7}, {%8,%9}, {%0,%1,%2,%3};"
        : "+f"(c[0]), "+f"(c[1]), "+f"(c[2]), "+f"(c[3])
        : "r"(a[0]), "r"(a[1]), "r"(a[2]), "r"(a[3]), "r"(b[0]), "r"(b[1]));
}
__device__ __forceinline__ uint32_t pack_bf16(float a, float b) {
    __nv_bfloat162 t = __floats2bfloat162_rn(a, b);
    return *(uint32_t*)&t;
}
__device__ __forceinline__ void split_pack(float a, float b, uint32_t& hi, uint32_t& lo) {
    __nv_bfloat16 ah = __float2bfloat16_rn(a);
    __nv_bfloat16 bh = __float2bfloat16_rn(b);
    float al = a - __bfloat162float(ah);
    float bl = b - __bfloat162float(bh);
    __nv_bfloat162 th; th.x = ah; th.y = bh;
    hi = *(uint32_t*)&th;
    lo = pack_bf16(al, bl);
}

// ---------------- split / fused transpose-split kernels ---------------------
__global__ __launch_bounds__(256) void split_kernel(
    const float4* __restrict__ in, __nv_bfloat16* __restrict__ hi,
    __nv_bfloat16* __restrict__ lo, int n4)
{
    int i = blockIdx.x * blockDim.x + threadIdx.x;
    if (i >= n4) return;
    float4 v = in[i];
    float f[4] = {v.x, v.y, v.z, v.w};
    __nv_bfloat162 h2[2], l2[2];
    #pragma unroll
    for (int j = 0; j < 4; j++) {
        __nv_bfloat16 h = __float2bfloat16_rn(f[j]);
        __nv_bfloat16 l = __float2bfloat16_rn(f[j] - __bfloat162float(h));
        ((__nv_bfloat16*)h2)[j] = h;
        ((__nv_bfloat16*)l2)[j] = l;
    }
    ((__nv_bfloat162*)hi)[2 * i + 0] = h2[0];
    ((__nv_bfloat162*)hi)[2 * i + 1] = h2[1];
    ((__nv_bfloat162*)lo)[2 * i + 0] = l2[0];
    ((__nv_bfloat162*)lo)[2 * i + 1] = l2[1];
}

// all 4 weights: W[K,N] fp32 -> Th/Tl [N,K] bf16 ; blockIdx.z picks the weight
__global__ __launch_bounds__(256) void transpose_split4_kernel(
    const float* __restrict__ W0, const float* __restrict__ W1,
    const float* __restrict__ W2, const float* __restrict__ W3,
    __nv_bfloat16* __restrict__ Th, __nv_bfloat16* __restrict__ Tl)
{
    __shared__ float t[32][33];
    const int z = blockIdx.z;
    const float* W = (z == 0) ? W0 : (z == 1) ? W1 : (z == 2) ? W2 : W3;
    __nv_bfloat16* Tho = Th + (size_t)z * DIM * DIM;
    __nv_bfloat16* Tlo = Tl + (size_t)z * DIM * DIM;
    const int tx = threadIdx.x & 31, ty = threadIdx.x >> 5;
    const int bx = blockIdx.x * 32, by = blockIdx.y * 32;
    #pragma unroll
    for (int s = 0; s < 4; s++)
        t[ty + s * 8][tx] = W[(size_t)(by + ty + s * 8) * DIM + bx + tx];
    __syncthreads();
    #pragma unroll
    for (int s = 0; s < 4; s++) {
        float v = t[tx][ty + s * 8];
        __nv_bfloat16 h = __float2bfloat16_rn(v);
        __nv_bfloat16 l = __float2bfloat16_rn(v - __bfloat162float(h));
        size_t o = (size_t)(bx + ty + s * 8) * DIM + by + tx;
        Tho[o] = h; Tlo[o] = l;
    }
}

// ---------------- shared GEMM plumbing (K=32 physical chunks) --------------
// Per chunk: load Ah/Al/Bh/Bl 128x32 tiles once, run all 3 products.
#define GS2   40                          // row stride (elems) = 80 B
#define GT2   (128 * GS2 * 2)             // 10240 B per tile
#define GB2   (4 * GT2)                   // buffer: Ah,Al,Bh,Bl = 40960 B
#define GEMM_SMEM (2 * GB2)               // 81920 B
#define NCH2  (DIM / 32)                  // 32 chunks

#define ISSUE_CHUNK2(c, buf, bRowBase) { \
    const int ko_ = (c) * 32; \
    uint32_t s0 = sbase + (buf) * GB2; \
    _Pragma("unroll") \
    for (int i = 0; i < 8; i++) { \
        int tile = i >> 1; \
        int idx = tid + (i & 1) * 256; \
        int row = idx >> 2, seg = idx & 3; \
        const __nv_bfloat16* src; \
        size_t gr; \
        if      (tile == 0) { src = Ah; gr = (size_t)(blockRow + row); } \
        else if (tile == 1) { src = Al; gr = (size_t)(blockRow + row); } \
        else if (tile == 2) { src = Bh; gr = (size_t)((bRowBase) + row); } \
        else                { src = Bl; gr = (size_t)((bRowBase) + row); } \
        cp_async16(s0 + tile * GT2 + row * 80 + seg * 16, \
                   src + gr * DIM + ko_ + seg * 8); \
    } }

#define GEMM_MAINLOOP() \
    ISSUE_CHUNK2(0, 0, blockCol); \
    cp_commit(); \
    for (int c = 0; c < NCH2; c++) { \
        if (c + 1 < NCH2) { ISSUE_CHUNK2(c + 1, (c + 1) & 1, blockCol); } \
        cp_commit(); \
        if (c + 1 < NCH2) cp_wait<1>(); else cp_wait<0>(); \
        __syncthreads(); \
        const uint32_t s0 = sbase + (c & 1) * GB2; \
        _Pragma("unroll") \
        for (int kk = 0; kk < 2; kk++) { \
            uint32_t ah[4][4], al[4][4], bhf[2][4], blf[2][4]; \
            _Pragma("unroll") \
            for (int mi = 0; mi < 4; mi++) { \
                uint32_t ao = ((aRow + mi * 16) * GS2 + kk * 16 + aCol) * 2; \
                ldsm4(ah[mi], s0 + ao); \
                ldsm4(al[mi], s0 + GT2 + ao); \
            } \
            _Pragma("unroll") \
            for (int np = 0; np < 2; np++) { \
                uint32_t bo = ((bRow + np * 16) * GS2 + kk * 16 + bCol) * 2; \
                ldsm4(bhf[np], s0 + 2 * GT2 + bo); \
                ldsm4(blf[np], s0 + 3 * GT2 + bo); \
            } \
            _Pragma("unroll") \
            for (int mi = 0; mi < 4; mi++) \
                _Pragma("unroll") \
                for (int ni = 0; ni < 4; ni++) { \
                    mma16816(acc[mi][ni], ah[mi], &bhf[ni >> 1][(ni & 1) * 2]); \
                    mma16816(acc[mi][ni], ah[mi], &blf[ni >> 1][(ni & 1) * 2]); \
                    mma16816(acc[mi][ni], al[mi], &bhf[ni >> 1][(ni & 1) * 2]); \
                } \
        } \
        __syncthreads(); \
    }

// ---------------- fused QKV GEMM: writes bf16 hi/lo, Q scaled by 0.125 -----
__global__ __launch_bounds__(256, 1)
void gemm_qkv_kernel(const __nv_bfloat16* __restrict__ Ah,
                     const __nv_bfloat16* __restrict__ Al,
                     const __nv_bfloat16* __restrict__ Bh,
                     const __nv_bfloat16* __restrict__ Bl,
                     const float* __restrict__ bq,
                     const float* __restrict__ bk,
                     const float* __restrict__ bv,
                     __nv_bfloat16* __restrict__ Ch,
                     __nv_bfloat16* __restrict__ Cl)
{
    extern __shared__ char smem[];
    const uint32_t sbase = smem_u32(smem);
    const int tid  = threadIdx.x;
    const int wid  = tid >> 5;
    const int lane = tid & 31;
    const int blockRow = blockIdx.y * 128;
    const int blockCol = blockIdx.x * 128;      // 0..2944
    const int wrow = (wid >> 2) * 64;
    const int wcol = (wid & 3) * 32;

    const float scale = (blockCol < DIM) ? 0.125f : 1.0f;
    const float* bsel;
    int cb;
    if (blockCol < DIM)            { bsel = bq; cb = blockCol; }
    else if (blockCol < 2 * DIM)   { bsel = bk; cb = blockCol - DIM; }
    else                           { bsel = bv; cb = blockCol - 2 * DIM; }

    float acc[4][4][4];
    #pragma unroll
    for (int mi = 0; mi < 4; mi++)
        #pragma unroll
        for (int ni = 0; ni < 4; ni++)
            #pragma unroll
            for (int j = 0; j < 4; j++) acc[mi][ni][j] = 0.f;

    const int aRow = wrow + (lane & 15);
    const int aCol = (lane >> 4) * 8;
    const int bRow = wcol + (lane >> 4) * 8 + (lane & 7);
    const int bCol = ((lane >> 3) & 1) * 8;

    GEMM_MAINLOOP();

    #pragma unroll
    for (int mi = 0; mi < 4; mi++) {
        const int r0 = blockRow + wrow + mi * 16 + (lane >> 2);
        #pragma unroll
        for (int ni = 0; ni < 4; ni++) {
            const int cc = wcol + ni * 8 + 2 * (lane & 3);
            float2 bv2 = *(const float2*)(bsel + cb + cc);
            const int gc = blockCol + cc;
            float v0x = (acc[mi][ni][0] + bv2.x) * scale;
            float v0y = (acc[mi][ni][1] + bv2.y) * scale;
            float v1x = (acc[mi][ni][2] + bv2.x) * scale;
            float v1y = (acc[mi][ni][3] + bv2.y) * scale;
            uint32_t h0, l0, h1, l1;
            split_pack(v0x, v0y, h0, l0);
            split_pack(v1x, v1y, h1, l1);
            *(uint32_t*)(Ch + (size_t)r0 * NQKV + gc)       = h0;
            *(uint32_t*)(Cl + (size_t)r0 * NQKV + gc)       = l0;
            *(uint32_t*)(Ch + (size_t)(r0 + 8) * NQKV + gc) = h1;
            *(uint32_t*)(Cl + (size_t)(r0 + 8) * NQKV + gc) = l1;
        }
    }
}

// ---------------- O-projection GEMM: fp32 out + bias -----------------------
__global__ __launch_bounds__(256, 1)
void gemm_mma_kernel(const __nv_bfloat16* __restrict__ Ah,
                     const __nv_bfloat16* __restrict__ Al,
                     const __nv_bfloat16* __restrict__ Bh,
                     const __nv_bfloat16* __restrict__ Bl,
                     const float* __restrict__ bias, float* __restrict__ C)
{
    extern __shared__ char smem[];
    const uint32_t sbase = smem_u32(smem);
    const int tid  = threadIdx.x;
    const int wid  = tid >> 5;
    const int lane = tid & 31;
    const int blockRow = blockIdx.y * 128;
    const int blockCol = blockIdx.x * 128;
    const int wrow = (wid >> 2) * 64;
    const int wcol = (wid & 3) * 32;

    float acc[4][4][4];
    #pragma unroll
    for (int mi = 0; mi < 4; mi++)
        #pragma unroll
        for (int ni = 0; ni < 4; ni++)
            #pragma unroll
            for (int j = 0; j < 4; j++) acc[mi][ni][j] = 0.f;

    const int aRow = wrow + (lane & 15);
    const int aCol = (lane >> 4) * 8;
    const int bRow = wcol + (lane >> 4) * 8 + (lane & 7);
    const int bCol = ((lane >> 3) & 1) * 8;

    GEMM_MAINLOOP();

    #pragma unroll
    for (int mi = 0; mi < 4; mi++) {
        const int r0 = blockRow + wrow + mi * 16 + (lane >> 2);
        #pragma unroll
        for (int ni = 0; ni < 4; ni++) {
            const int c0 = blockCol + wcol + ni * 8 + 2 * (lane & 3);
            float2 bv = *(const float2*)(bias + c0);
            float2 v0 = { acc[mi][ni][0] + bv.x, acc[mi][ni][1] + bv.y };
            float2 v1 = { acc[mi][ni][2] + bv.x, acc[mi][ni][3] + bv.y };
            *(float2*)(C + (size_t)r0 * DIM + c0)       = v0;
            *(float2*)(C + (size_t)(r0 + 8) * DIM + c0) = v1;
        }
    }
}

// ---------------- Flash attention (bf16-split mma, causal, softmax-one) ----
#define FQS 72
#define FQ_ELE   (128 * FQS)
#define FKV_ELE  (64 * FQS)
#define FKVBUF   (4 * FKV_ELE)
#define FLASH_SMEM ((2 * FQ_ELE + 2 * FKVBUF) * 2)   // 110592 bytes

__global__ __launch_bounds__(128) void flash_mma_kernel(
    const __nv_bfloat16* __restrict__ QKVh,
    const __nv_bfloat16* __restrict__ QKVl,
    __nv_bfloat16* __restrict__ Ch,
    __nv_bfloat16* __restrict__ Cl)
{
    const int bx   = blockIdx.x;          // 0..7
    const int bh   = blockIdx.y;          // 0..31
    const int b    = bh >> 4;
    const int h    = bh & 15;
    const int tid  = threadIdx.x;
    const int wid  = tid >> 5;
    const int lane = tid & 31;
    const int wrow = wid * 32;
    const size_t rowbase = (size_t)b * SEQ;
    const int qcol = h * HD;
    const int kcol = qcol + DIM;
    const int vcol = qcol + 2 * DIM;

    extern __shared__ __nv_bfloat16 fsm[];
    const uint32_t uQh = smem_u32(fsm);
    const uint32_t uQl = uQh + FQ_ELE * 2;
    const uint32_t uKV0 = uQl + FQ_ELE * 2;
    #define KV_KH(bb) (uKV0 + (bb) * FKVBUF * 2)
    #define KV_KL(bb) (KV_KH(bb) + FKV_ELE * 2)
    #define KV_VH(bb) (KV_KH(bb) + 2 * FKV_ELE * 2)
    #define KV_VL(bb) (KV_KH(bb) + 3 * FKV_ELE * 2)

    #define ISSUE_Q(qb) { \
        _Pragma("unroll") \
        for (int i = 0; i < 8; i++) { \
            int idx = tid + i * 128; \
            int r = idx >> 3, seg = idx & 7; \
            size_t g = (rowbase + (qb) + r) * NQKV + qcol + seg * 8; \
            cp_async16(uQh + r * 144 + seg * 16, QKVh + g); \
            cp_async16(uQl + r * 144 + seg * 16, QKVl + g); \
        } }

    #define ISSUE_KV(kb, bb) { \
        _Pragma("unroll") \
        for (int i = 0; i < 4; i++) { \
            int idx = tid + i * 128; \
            int r = idx >> 3, seg = idx & 7; \
            size_t gk = (rowbase + (kb) + r) * NQKV + kcol + seg * 8; \
            size_t gv = (rowbase + (kb) + r) * NQKV + vcol + seg * 8; \
            uint32_t so = r * 144 + seg * 16; \
            cp_async16(KV_KH(bb) + so, QKVh + gk); \
            cp_async16(KV_KL(bb) + so, QKVl + gk); \
            cp_async16(KV_VH(bb) + so, QKVh + gv); \
            cp_async16(KV_VL(bb) + so, QKVl + gv); \
        } }

    for (int t = 0; t < 2; t++) {
        const int qt = (t == 0) ? bx : (15 - bx);
        const int qbase = qt * 128;

        float sa[2][8][4];
        float oa[2][8][4];
        float m[4], l[4];
        #pragma unroll
        for (int mi = 0; mi < 2; mi++)
            #pragma unroll
            for (int ni = 0; ni < 8; ni++)
                #pragma unroll
                for (int j = 0; j < 4; j++) oa[mi][ni][j] = 0.f;
        #pragma unroll
        for (int i = 0; i < 4; i++) { m[i] = -INFINITY; l[i] = 0.f; }

        __syncthreads();
        ISSUE_Q(qbase);
        ISSUE_KV(0, 0);
        cp_commit();

        const int nkt = 2 * qt + 2;
        for (int kt = 0; kt < nkt; kt++) {
            const int kbase = kt * 64;
            if (kt + 1 < nkt) { ISSUE_KV((kt + 1) * 64, (kt + 1) & 1); }
            cp_commit();
            if (kt + 1 < nkt) cp_wait<1>(); else cp_wait<0>();
            __syncthreads();

            const int bb = kt & 1;
            const uint32_t uKh = KV_KH(bb), uKl = KV_KL(bb);
            const uint32_t uVh = KV_VH(bb), uVl = KV_VL(bb);

            #pragma unroll
            for (int mi = 0; mi < 2; mi++)
                #pragma unroll
                for (int ni = 0; ni < 8; ni++)
                    #pragma unroll
                    for (int j = 0; j < 4; j++) sa[mi][ni][j] = 0.f;

            #pragma unroll
            for (int kk = 0; kk < 4; kk++) {
                uint32_t aqh[2][4], aql[2][4];
                #pragma unroll
                for (int mi = 0; mi < 2; mi++) {
                    uint32_t ao = ((wrow + mi * 16 + (lane & 15)) * FQS +
                                   kk * 16 + (lane >> 4) * 8) * 2;
                    ldsm4(aqh[mi], uQh + ao);
                    ldsm4(aql[mi], uQl + ao);
                }
                #pragma unroll
                for (int g = 0; g < 4; g++) {
                    uint32_t bh_[4], bl_[4];
                    uint32_t bo = ((g * 16 + (lane >> 4) * 8 + (lane & 7)) * FQS +
                                   kk * 16 + ((lane >> 3) & 1) * 8) * 2;
                    ldsm4(bh_, uKh + bo);
                    ldsm4(bl_, uKl + bo);
                    #pragma unroll
                    for (int mi = 0; mi < 2; mi++)
                        #pragma unroll
                        for (int p = 0; p < 2; p++) {
                            int ni = g * 2 + p;
                            mma16816(sa[mi][ni], aqh[mi], &bh_[p * 2]);
                            mma16816(sa[mi][ni], aqh[mi], &bl_[p * 2]);
                            mma16816(sa[mi][ni], aql[mi], &bh_[p * 2]);
                        }
                }
            }

            if (kbase + 63 > qbase + wrow) {
                #pragma unroll
                for (int mi = 0; mi < 2; mi++)
                    #pragma unroll
                    for (int ni = 0; ni < 8; ni++)
                        #pragma unroll
                        for (int j = 0; j < 4; j++) {
                            int qrow = qbase + wrow + mi * 16 + (lane >> 2) + (j >> 1) * 8;
                            int kc = kbase + ni * 8 + 2 * (lane & 3) + (j & 1);
                            if (kc > qrow) sa[mi][ni][j] = -INFINITY;
                        }
            }

            #pragma unroll
            for (int mi = 0; mi < 2; mi++)
                #pragma unroll
                for (int rh = 0; rh < 2; rh++) {
                    const int ri = mi * 2 + rh;
                    float rmax = -INFINITY;
                    #pragma unroll
                    for (int ni = 0; ni < 8; ni++)
                        rmax = fmaxf(rmax, fmaxf(sa[mi][ni][rh * 2], sa[mi][ni][rh * 2 + 1]));
                    rmax = fmaxf(rmax, __shfl_xor_sync(0xffffffffu, rmax, 1));
                    rmax = fmaxf(rmax, __shfl_xor_sync(0xffffffffu, rmax, 2));
                    float mnew = fmaxf(m[ri], rmax);
                    float corr = __expf(m[ri] - mnew);
                    float sum = 0.f;
                    #pragma unroll
                    for (int ni = 0; ni < 8; ni++)
                        #pragma unroll
                        for (int j2 = 0; j2 < 2; j2++) {
                            float p = __expf(sa[mi][ni][rh * 2 + j2] - mnew);
                            sa[mi][ni][rh * 2 + j2] = p;
                            sum += p;
                        }
                    sum += __shfl_xor_sync(0xffffffffu, sum, 1);
                    sum += __shfl_xor_sync(0xffffffffu, sum, 2);
                    l[ri] = l[ri] * corr + sum;
                    m[ri] = mnew;
                    #pragma unroll
                    for (int ni = 0; ni < 8; ni++)
                        #pragma unroll
                        for (int j2 = 0; j2 < 2; j2++)
                            oa[mi][ni][rh * 2 + j2] *= corr;
                }

            #pragma unroll
            for (int kk = 0; kk < 4; kk++) {
                uint32_t ph[2][4], pl[2][4];
                #pragma unroll
                for (int mi = 0; mi < 2; mi++) {
                    split_pack(sa[mi][2 * kk][0],     sa[mi][2 * kk][1],     ph[mi][0], pl[mi][0]);
                    split_pack(sa[mi][2 * kk][2],     sa[mi][2 * kk][3],     ph[mi][1], pl[mi][1]);
                    split_pack(sa[mi][2 * kk + 1][0], sa[mi][2 * kk + 1][1], ph[mi][2], pl[mi][2]);
                    split_pack(sa[mi][2 * kk + 1][2], sa[mi][2 * kk + 1][3], ph[mi][3], pl[mi][3]);
                }
                #pragma unroll
                for (int dg = 0; dg < 4; dg++) {
                    uint32_t bvh[4], bvl[4];
                    uint32_t bo = ((kk * 16 + ((lane >> 3) & 1) * 8 + (lane & 7)) * FQS +
                                   dg * 16 + (lane >> 4) * 8) * 2;
                    ldsm4t(bvh, uVh + bo);
                    ldsm4t(bvl, uVl + bo);
                    #pragma unroll
                    for (int mi = 0; mi < 2; mi++)
                        #pragma unroll
                        for (int p = 0; p < 2; p++) {
                            int ni = dg * 2 + p;
                            mma16816(oa[mi][ni], ph[mi], &bvh[p * 2]);
                            mma16816(oa[mi][ni], ph[mi], &bvl[p * 2]);
                            mma16816(oa[mi][ni], pl[mi], &bvh[p * 2]);
                        }
                }
            }
            __syncthreads();
        }

        #pragma unroll
        for (int mi = 0; mi < 2; mi++) {
            const float inv0 = 1.f / (1.f + l[mi * 2 + 0]);
            const float inv1 = 1.f / (1.f + l[mi * 2 + 1]);
            const int r0 = qbase + wrow + mi * 16 + (lane >> 2);
            #pragma unroll
            for (int ni = 0; ni < 8; ni++) {
                const int c0 = ni * 8 + 2 * (lane & 3);
                uint32_t h0, l0, h1, l1;
                split_pack(oa[mi][ni][0] * inv0, oa[mi][ni][1] * inv0, h0, l0);
                split_pack(oa[mi][ni][2] * inv1, oa[mi][ni][3] * inv1, h1, l1);
                size_t o0 = (rowbase + r0) * DIM + qcol + c0;
                size_t o1 = (rowbase + r0 + 8) * DIM + qcol + c0;
                *(uint32_t*)(Ch + o0) = h0;
                *(uint32_t*)(Cl + o0) = l0;
                *(uint32_t*)(Ch + o1) = h1;
                *(uint32_t*)(Cl + o1) = l1;
            }
        }
    }
}

// ---------------- launcher -------------------------------------------------
extern "C" void kernel_launch(void* const* d_in, const int* in_sizes, int n_in,
                              void* d_out, int out_size)
{
    const float* x  = (const float*)d_in[0];
    const float* Wq = (const float*)d_in[1];
    const float* bq = (const float*)d_in[2];
    const float* Wk = (const float*)d_in[3];
    const float* bk = (const float*)d_in[4];
    const float* Wv = (const float*)d_in[5];
    const float* bv = (const float*)d_in[6];
    const float* Wo = (const float*)d_in[7];
    const float* bo = (const float*)d_in[8];
    float* out = (float*)d_out;

    __nv_bfloat16 *xh, *xl, *wth, *wtl, *qkvh, *qkvl;
    cudaGetSymbolAddress((void**)&xh,   g_xh);
    cudaGetSymbolAddress((void**)&xl,   g_xl);
    cudaGetSymbolAddress((void**)&wth,  g_wth);
    cudaGetSymbolAddress((void**)&wtl,  g_wtl);
    cudaGetSymbolAddress((void**)&qkvh, g_qkvh);
    cudaGetSymbolAddress((void**)&qkvl, g_qkvl);

    cudaFuncSetAttribute(flash_mma_kernel,
                         cudaFuncAttributeMaxDynamicSharedMemorySize, FLASH_SMEM);
    cudaFuncSetAttribute(gemm_qkv_kernel,
                         cudaFuncAttributeMaxDynamicSharedMemorySize, GEMM_SMEM);
    cudaFuncSetAttribute(gemm_mma_kernel,
                         cudaFuncAttributeMaxDynamicSharedMemorySize, GEMM_SMEM);

    const int n4 = MROWS * DIM / 4;

    split_kernel<<<(n4 + 255) / 256, 256>>>((const float4*)x, xh, xl, n4);
    dim3 tg(32, 32, 4);
    transpose_split4_kernel<<<tg, 256>>>(Wq, Wk, Wv, Wo, wth, wtl);

    dim3 gqkv(NQKV / 128, MROWS / 128);        // (24, 32)
    gemm_qkv_kernel<<<gqkv, 256, GEMM_SMEM>>>(xh, xl, wth, wtl, bq, bk, bv, qkvh, qkvl);

    dim3 attnGrid(SEQ / 256, BATCH * NHEAD);   // (8, 32)
    flash_mma_kernel<<<attnGrid, 128, FLASH_SMEM>>>(qkvh, qkvl, xh, xl);

    dim3 go(DIM / 128, MROWS / 128);           // (8, 32)
    gemm_mma_kernel<<<go, 256, GEMM_SMEM>>>(xh, xl, wth + 3 * DIM * DIM, wtl + 3 * DIM * DIM, bo, out);
}